// round 1
// baseline (speedup 1.0000x reference)
#include <cuda_runtime.h>

// Problem shapes (fixed by the dataset)
#define BATCH 8
#define LQ    1024
#define LK    1024
#define DIM   512
#define CH    512
#define KW_   3

// ---------------------------------------------------------------------------
// Scratch (device globals — no allocation allowed in kernel_launch)
// ---------------------------------------------------------------------------
__device__ float g_Wre[3 * CH * DIM];            // Wre[w][c][d] = W_kernel[d, c*3+w]  (3 MB)
__device__ float g_U[BATCH * LK * DIM];          // U[b][j][d]                          (16 MB)
__device__ float g_bbj[BATCH * LK];              // b_kernel-derived bias per (b,j)
__device__ float g_qb[BATCH * LQ];               // q@W_bias + b_bias per (b,i)

// ---------------------------------------------------------------------------
// Repack W_kernel[d, c*3+w] -> Wre[w][c][d] so stage A is a clean GEMM
// ---------------------------------------------------------------------------
__global__ void repack_kernel(const float* __restrict__ W) {
    int idx = blockIdx.x * blockDim.x + threadIdx.x;
    const int total = 3 * CH * DIM;
    if (idx < total) {
        int w = idx / (CH * DIM);
        int r = idx % (CH * DIM);
        int c = r / DIM;
        int d = r % DIM;
        g_Wre[idx] = W[d * (CH * KW_) + c * KW_ + w];
    }
}

// ---------------------------------------------------------------------------
// qb[b,i] = q[b,i,:] . W_bias + b_bias        (one warp per row)
// ---------------------------------------------------------------------------
__global__ void qb_kernel(const float* __restrict__ q,
                          const float* __restrict__ Wb,
                          const float* __restrict__ bb) {
    int warp = (blockIdx.x * blockDim.x + threadIdx.x) >> 5;
    int lane = threadIdx.x & 31;
    if (warp >= BATCH * LQ) return;
    const float* qr = q + (size_t)warp * DIM;
    float s = 0.f;
    #pragma unroll 4
    for (int d = lane; d < DIM; d += 32) s += qr[d] * Wb[d];
    #pragma unroll
    for (int o = 16; o; o >>= 1) s += __shfl_down_sync(0xFFFFFFFFu, s, o);
    if (lane == 0) g_qb[warp] = s + bb[0];
}

// ---------------------------------------------------------------------------
// bbj[b,j] = sum_{w,c} b_kernel[c*3+w] * k[b, j+w-1, c]   (one warp per row)
// ---------------------------------------------------------------------------
__global__ void bbj_kernel(const float* __restrict__ K,
                           const float* __restrict__ bk) {
    int warp = (blockIdx.x * blockDim.x + threadIdx.x) >> 5;
    int lane = threadIdx.x & 31;
    if (warp >= BATCH * LK) return;
    int b = warp / LK;
    int j = warp % LK;
    float s = 0.f;
    #pragma unroll
    for (int w = 0; w < 3; ++w) {
        int r = j + w - 1;
        if (r < 0 || r >= LK) continue;
        const float* kr = K + ((size_t)b * LK + r) * CH;
        #pragma unroll 4
        for (int c = lane; c < CH; c += 32) s += bk[c * KW_ + w] * kr[c];
    }
    #pragma unroll
    for (int o = 16; o; o >>= 1) s += __shfl_down_sync(0xFFFFFFFFu, s, o);
    if (lane == 0) g_bbj[warp] = s;
}

// ---------------------------------------------------------------------------
// Stage A: U[b][j][d] = sum_w sum_c k[b][j+w-1][c] * Wre[w][c][d]
//   per-batch GEMM, M=LK (j), N=DIM (d), K=CH (c), accumulated over 3 shifts
//   128x128 tile, BK=16, 256 threads, 8x8 per-thread micro-tile
// ---------------------------------------------------------------------------
__global__ __launch_bounds__(256) void gemmA_kernel(const float* __restrict__ K) {
    const int b  = blockIdx.z;
    const int jt = blockIdx.y * 128;
    const int dt = blockIdx.x * 128;

    __shared__ float As[16][128];   // As[c][j]
    __shared__ float Bs[16][128];   // Bs[c][d]

    const int tid = threadIdx.x;
    const int tx  = tid & 15;       // n (d) direction
    const int ty  = tid >> 4;       // m (j) direction

    float acc[8][8];
    #pragma unroll
    for (int mi = 0; mi < 8; ++mi)
        #pragma unroll
        for (int ni = 0; ni < 8; ++ni) acc[mi][ni] = 0.f;

    const float* Kb = K + (size_t)b * LK * CH;

    for (int w = 0; w < 3; ++w) {
        const float* Bw = g_Wre + (size_t)w * CH * DIM;
        for (int kt = 0; kt < CH; kt += 16) {
            // --- load A tile (128 j-rows x 16 c) transposed into As[c][j] ---
            #pragma unroll
            for (int u = 0; u < 2; ++u) {
                int f    = tid + u * 256;          // 0..511 float4 slots
                int row  = f >> 2;                 // 0..127 (j within tile)
                int col4 = f & 3;                  // 0..3 (c group of 4)
                int jg   = jt + row + w - 1;
                float4 v = make_float4(0.f, 0.f, 0.f, 0.f);
                if (jg >= 0 && jg < LK)
                    v = *reinterpret_cast<const float4*>(Kb + (size_t)jg * CH + kt + col4 * 4);
                As[col4 * 4 + 0][row] = v.x;
                As[col4 * 4 + 1][row] = v.y;
                As[col4 * 4 + 2][row] = v.z;
                As[col4 * 4 + 3][row] = v.w;

                // --- load B tile (16 c-rows x 128 d) directly ---
                int fr = f >> 5;                   // 0..15 (c row)
                int fc = f & 31;                   // 0..31 (d group of 4)
                float4 bv = *reinterpret_cast<const float4*>(
                    Bw + (size_t)(kt + fr) * DIM + dt + fc * 4);
                *reinterpret_cast<float4*>(&Bs[fr][fc * 4]) = bv;
            }
            __syncthreads();

            #pragma unroll
            for (int kk = 0; kk < 16; ++kk) {
                float a_reg[8], b_reg[8];
                *reinterpret_cast<float4*>(&a_reg[0]) = *reinterpret_cast<float4*>(&As[kk][ty * 8]);
                *reinterpret_cast<float4*>(&a_reg[4]) = *reinterpret_cast<float4*>(&As[kk][ty * 8 + 4]);
                *reinterpret_cast<float4*>(&b_reg[0]) = *reinterpret_cast<float4*>(&Bs[kk][tx * 8]);
                *reinterpret_cast<float4*>(&b_reg[4]) = *reinterpret_cast<float4*>(&Bs[kk][tx * 8 + 4]);
                #pragma unroll
                for (int mi = 0; mi < 8; ++mi)
                    #pragma unroll
                    for (int ni = 0; ni < 8; ++ni)
                        acc[mi][ni] += a_reg[mi] * b_reg[ni];
            }
            __syncthreads();
        }
    }

    // store U
    #pragma unroll
    for (int mi = 0; mi < 8; ++mi) {
        int j = jt + ty * 8 + mi;
        float* Urow = g_U + ((size_t)b * LK + j) * DIM + dt + tx * 8;
        *reinterpret_cast<float4*>(Urow)     = *reinterpret_cast<float4*>(&acc[mi][0]);
        *reinterpret_cast<float4*>(Urow + 4) = *reinterpret_cast<float4*>(&acc[mi][4]);
    }
}

// ---------------------------------------------------------------------------
// Stage B: out[b][i][j] = sum_d q[b][i][d] * U[b][j][d] + qb[b,i] + bbj[b,j] + bias_b
//   per-batch NT GEMM, M=LQ (i), N=LK (j), K=DIM (d)
// ---------------------------------------------------------------------------
__global__ __launch_bounds__(256) void gemmB_kernel(const float* __restrict__ Q,
                                                    const float* __restrict__ biasb,
                                                    float* __restrict__ out) {
    const int b  = blockIdx.z;
    const int it = blockIdx.y * 128;
    const int jt = blockIdx.x * 128;

    __shared__ float As[16][128];   // As[d][i]
    __shared__ float Bs[16][128];   // Bs[d][j]

    const int tid = threadIdx.x;
    const int tx  = tid & 15;       // j direction
    const int ty  = tid >> 4;       // i direction

    float acc[8][8];
    #pragma unroll
    for (int mi = 0; mi < 8; ++mi)
        #pragma unroll
        for (int ni = 0; ni < 8; ++ni) acc[mi][ni] = 0.f;

    const float* Ab = Q   + (size_t)b * LQ * DIM;
    const float* Bb = g_U + (size_t)b * LK * DIM;

    for (int kt = 0; kt < DIM; kt += 16) {
        #pragma unroll
        for (int u = 0; u < 2; ++u) {
            int f    = tid + u * 256;
            int row  = f >> 2;
            int col4 = f & 3;
            float4 av = *reinterpret_cast<const float4*>(Ab + (size_t)(it + row) * DIM + kt + col4 * 4);
            As[col4 * 4 + 0][row] = av.x;
            As[col4 * 4 + 1][row] = av.y;
            As[col4 * 4 + 2][row] = av.z;
            As[col4 * 4 + 3][row] = av.w;
            float4 bv = *reinterpret_cast<const float4*>(Bb + (size_t)(jt + row) * DIM + kt + col4 * 4);
            Bs[col4 * 4 + 0][row] = bv.x;
            Bs[col4 * 4 + 1][row] = bv.y;
            Bs[col4 * 4 + 2][row] = bv.z;
            Bs[col4 * 4 + 3][row] = bv.w;
        }
        __syncthreads();

        #pragma unroll
        for (int kk = 0; kk < 16; ++kk) {
            float a_reg[8], b_reg[8];
            *reinterpret_cast<float4*>(&a_reg[0]) = *reinterpret_cast<float4*>(&As[kk][ty * 8]);
            *reinterpret_cast<float4*>(&a_reg[4]) = *reinterpret_cast<float4*>(&As[kk][ty * 8 + 4]);
            *reinterpret_cast<float4*>(&b_reg[0]) = *reinterpret_cast<float4*>(&Bs[kk][tx * 8]);
            *reinterpret_cast<float4*>(&b_reg[4]) = *reinterpret_cast<float4*>(&Bs[kk][tx * 8 + 4]);
            #pragma unroll
            for (int mi = 0; mi < 8; ++mi)
                #pragma unroll
                for (int ni = 0; ni < 8; ++ni)
                    acc[mi][ni] += a_reg[mi] * b_reg[ni];
        }
        __syncthreads();
    }

    const float bB = biasb[0];
    float bbv[8];
    *reinterpret_cast<float4*>(&bbv[0]) =
        *reinterpret_cast<const float4*>(g_bbj + b * LK + jt + tx * 8);
    *reinterpret_cast<float4*>(&bbv[4]) =
        *reinterpret_cast<const float4*>(g_bbj + b * LK + jt + tx * 8 + 4);

    #pragma unroll
    for (int mi = 0; mi < 8; ++mi) {
        int i = it + ty * 8 + mi;
        float qb = g_qb[b * LQ + i];
        float o[8];
        #pragma unroll
        for (int ni = 0; ni < 8; ++ni)
            o[ni] = acc[mi][ni] + qb + bbv[ni] + bB;
        float* orow = out + ((size_t)b * LQ + i) * LK + jt + tx * 8;
        *reinterpret_cast<float4*>(orow)     = *reinterpret_cast<float4*>(&o[0]);
        *reinterpret_cast<float4*>(orow + 4) = *reinterpret_cast<float4*>(&o[4]);
    }
}

// ---------------------------------------------------------------------------
extern "C" void kernel_launch(void* const* d_in, const int* in_sizes, int n_in,
                              void* d_out, int out_size) {
    const float* q     = (const float*)d_in[0];   // (8,1024,512)
    const float* k     = (const float*)d_in[1];   // (8,1024,512)
    const float* W     = (const float*)d_in[2];   // (512,1536)
    const float* bk    = (const float*)d_in[3];   // (1536,)
    const float* Wb    = (const float*)d_in[4];   // (512,1)
    const float* bb    = (const float*)d_in[5];   // (1,)
    const float* biasb = (const float*)d_in[6];   // (1,)
    float* out = (float*)d_out;                   // (8,1024,1024)

    repack_kernel<<<(3 * CH * DIM + 255) / 256, 256>>>(W);
    qb_kernel<<<(BATCH * LQ) / 8, 256>>>(q, Wb, bb);     // 8 warps/block
    bbj_kernel<<<(BATCH * LK) / 8, 256>>>(k, bk);

    dim3 gA(DIM / 128, LK / 128, BATCH);                 // (4, 8, 8)
    gemmA_kernel<<<gA, 256>>>(k);

    dim3 gB(LK / 128, LQ / 128, BATCH);                  // (8, 8, 8)
    gemmB_kernel<<<gB, 256>>>(q, biasb, out);
}

// round 6
// speedup vs baseline: 1.2608x; 1.2608x over previous
#include <cuda_runtime.h>
#include <cuda_bf16.h>
#include <cstdint>

// Problem shapes (fixed by the dataset)
#define BATCH 8
#define LQ    1024
#define LK    1024
#define DIM   512
#define CH    512
#define KTOT  1536   // 3*CH

// ---------------------------------------------------------------------------
// Scratch (device globals — allocation-free). IMPORTANT: these must only be
// referenced from DEVICE code; taking their address in host code yields the
// host shadow symbol (silently "works" on GB300 via ATS and corrupts nothing
// visible — the round-3/4 bug).
// ---------------------------------------------------------------------------
__device__ __nv_bfloat16 g_qhi[BATCH * LQ * DIM];
__device__ __nv_bfloat16 g_qlo[BATCH * LQ * DIM];
__device__ __nv_bfloat16 g_khi[BATCH * LK * CH];
__device__ __nv_bfloat16 g_klo[BATCH * LK * CH];
__device__ __nv_bfloat16 g_Whi[DIM * KTOT];      // Wop[d][w*CH+c] = W[d, c*3+w]
__device__ __nv_bfloat16 g_Wlo[DIM * KTOT];
__device__ __nv_bfloat16 g_Uhi[BATCH * LK * DIM];
__device__ __nv_bfloat16 g_Ulo[BATCH * LK * DIM];
__device__ float g_bbj[BATCH * LK];
__device__ float g_qb[BATCH * LQ];

// ---------------------------------------------------------------------------
// mma.sync bf16 m16n8k16 (works on base sm_103 target — no tcgen05 needed)
// ---------------------------------------------------------------------------
__device__ __forceinline__ void mma16816(float* c,
                                         uint32_t a0, uint32_t a1, uint32_t a2, uint32_t a3,
                                         uint32_t b0, uint32_t b1) {
    asm volatile(
        "mma.sync.aligned.m16n8k16.row.col.f32.bf16.bf16.f32 "
        "{%0,%1,%2,%3}, {%4,%5,%6,%7}, {%8,%9}, {%0,%1,%2,%3};"
        : "+f"(c[0]), "+f"(c[1]), "+f"(c[2]), "+f"(c[3])
        : "r"(a0), "r"(a1), "r"(a2), "r"(a3), "r"(b0), "r"(b1));
}

// smem tile: 128 rows x 64 bytes (32 bf16), XOR-swizzled so fragment loads are
// bank-conflict-free:  phys = row*64 + (kb ^ (((row>>1)&3)<<4))
__device__ __forceinline__ uint32_t sw_off(int row, int kb) {
    return (uint32_t)(row * 64 + (kb ^ (((row >> 1) & 3) << 4)));
}

// Pack two floats into one u32 of bf16 hi parts; residuals out (register ops).
__device__ __forceinline__ uint32_t pack_hi(float a, float b, float& ra, float& rb) {
    __nv_bfloat16 ha = __float2bfloat16(a);
    __nv_bfloat16 hb = __float2bfloat16(b);
    ra = a - __bfloat162float(ha);
    rb = b - __bfloat162float(hb);
    return (uint32_t)__bfloat16_as_ushort(ha) |
           ((uint32_t)__bfloat16_as_ushort(hb) << 16);
}
__device__ __forceinline__ uint32_t pack_bf(float a, float b) {
    return (uint32_t)__bfloat16_as_ushort(__float2bfloat16(a)) |
           ((uint32_t)__bfloat16_as_ushort(__float2bfloat16(b)) << 16);
}

// ---------------------------------------------------------------------------
// fp32 -> bf16 hi/lo splits. Destinations are the device globals, referenced
// ONLY inside device code.
// ---------------------------------------------------------------------------
__device__ __forceinline__ void split_body(const float* __restrict__ s,
                                           __nv_bfloat16* hi, __nv_bfloat16* lo,
                                           int i) {
    float4 v = reinterpret_cast<const float4*>(s)[i];
    float rx, ry, rz, rw;
    uint32_t h01 = pack_hi(v.x, v.y, rx, ry);
    uint32_t h23 = pack_hi(v.z, v.w, rz, rw);
    reinterpret_cast<uint2*>(hi)[i] = make_uint2(h01, h23);
    reinterpret_cast<uint2*>(lo)[i] = make_uint2(pack_bf(rx, ry), pack_bf(rz, rw));
}

__global__ void split_q_kernel(const float* __restrict__ s) {
    int i = blockIdx.x * blockDim.x + threadIdx.x;
    if (i < BATCH * LQ * DIM / 4) split_body(s, g_qhi, g_qlo, i);
}
__global__ void split_k_kernel(const float* __restrict__ s) {
    int i = blockIdx.x * blockDim.x + threadIdx.x;
    if (i < BATCH * LK * CH / 4) split_body(s, g_khi, g_klo, i);
}

// W repack + split: Wop[d][w*CH+c] = W[d, c*3+w]
__global__ void wsplit_kernel(const float* __restrict__ W) {
    int idx = blockIdx.x * blockDim.x + threadIdx.x;
    if (idx >= DIM * KTOT) return;
    int d  = idx / KTOT;
    int wc = idx % KTOT;
    int w  = wc / CH;
    int c  = wc % CH;
    float f = W[d * KTOT + c * 3 + w];
    __nv_bfloat16 h = __float2bfloat16(f);
    g_Whi[idx] = h;
    g_Wlo[idx] = __float2bfloat16(f - __bfloat162float(h));
}

// qb[b,i] = q[b,i,:] . W_bias + b_bias
__global__ void qb_kernel(const float* __restrict__ q,
                          const float* __restrict__ Wb,
                          const float* __restrict__ bb) {
    int warp = (blockIdx.x * blockDim.x + threadIdx.x) >> 5;
    int lane = threadIdx.x & 31;
    if (warp >= BATCH * LQ) return;
    const float* qr = q + (size_t)warp * DIM;
    float s = 0.f;
    #pragma unroll 4
    for (int d = lane; d < DIM; d += 32) s += qr[d] * Wb[d];
    #pragma unroll
    for (int o = 16; o; o >>= 1) s += __shfl_down_sync(0xFFFFFFFFu, s, o);
    if (lane == 0) g_qb[warp] = s + bb[0];
}

// bbj[b,j] = sum_{w,c} b_kernel[c*3+w] * k[b, j+w-1, c]
__global__ void bbj_kernel(const float* __restrict__ K,
                           const float* __restrict__ bk) {
    int warp = (blockIdx.x * blockDim.x + threadIdx.x) >> 5;
    int lane = threadIdx.x & 31;
    if (warp >= BATCH * LK) return;
    int b = warp / LK;
    int j = warp % LK;
    float s = 0.f;
    #pragma unroll
    for (int w = 0; w < 3; ++w) {
        int r = j + w - 1;
        if (r < 0 || r >= LK) continue;
        const float* kr = K + ((size_t)b * LK + r) * CH;
        #pragma unroll 4
        for (int c = lane; c < CH; c += 32) s += bk[c * 3 + w] * kr[c];
    }
    #pragma unroll
    for (int o = 16; o; o >>= 1) s += __shfl_down_sync(0xFFFFFFFFu, s, o);
    if (lane == 0) g_bbj[warp] = s;
}

// ---------------------------------------------------------------------------
// Shared GEMM core: CTA 128x128, BK=32, 8 warps, warp tile 64x32.
// Split-bf16: acc += Ahi*Bhi + Ahi*Blo + Alo*Bhi  (fp32 accumulators)
// ---------------------------------------------------------------------------
#define TILE_BYTES (128 * 64)

struct Frags {
    uint32_t ah[4][4];
    uint32_t bh[4][2];
};

__device__ __forceinline__ void gemm_chunk(const uint8_t* sAhi, const uint8_t* sAlo,
                                           const uint8_t* sBhi, const uint8_t* sBlo,
                                           int wm, int wn, int g, int t,
                                           float acc[4][4][4]) {
    #pragma unroll
    for (int ks = 0; ks < 2; ++ks) {
        const int kb0 = ks * 32 + t * 4;
        Frags fr;
        #pragma unroll
        for (int mi = 0; mi < 4; ++mi) {
            int r = wm * 64 + mi * 16 + g;
            fr.ah[mi][0] = *(const uint32_t*)(sAhi + sw_off(r,     kb0));
            fr.ah[mi][1] = *(const uint32_t*)(sAhi + sw_off(r + 8, kb0));
            fr.ah[mi][2] = *(const uint32_t*)(sAhi + sw_off(r,     kb0 + 16));
            fr.ah[mi][3] = *(const uint32_t*)(sAhi + sw_off(r + 8, kb0 + 16));
        }
        #pragma unroll
        for (int ni = 0; ni < 4; ++ni) {
            int r = wn * 32 + ni * 8 + g;
            fr.bh[ni][0] = *(const uint32_t*)(sBhi + sw_off(r, kb0));
            fr.bh[ni][1] = *(const uint32_t*)(sBhi + sw_off(r, kb0 + 16));
        }
        // pass 1: hi*hi
        #pragma unroll
        for (int mi = 0; mi < 4; ++mi)
            #pragma unroll
            for (int ni = 0; ni < 4; ++ni)
                mma16816(acc[mi][ni], fr.ah[mi][0], fr.ah[mi][1], fr.ah[mi][2], fr.ah[mi][3],
                         fr.bh[ni][0], fr.bh[ni][1]);
        // pass 2: hi*lo (reuse ah)
        #pragma unroll
        for (int ni = 0; ni < 4; ++ni) {
            int r = wn * 32 + ni * 8 + g;
            uint32_t bl0 = *(const uint32_t*)(sBlo + sw_off(r, kb0));
            uint32_t bl1 = *(const uint32_t*)(sBlo + sw_off(r, kb0 + 16));
            #pragma unroll
            for (int mi = 0; mi < 4; ++mi)
                mma16816(acc[mi][ni], fr.ah[mi][0], fr.ah[mi][1], fr.ah[mi][2], fr.ah[mi][3],
                         bl0, bl1);
        }
        // pass 3: lo*hi (reuse bh)
        #pragma unroll
        for (int mi = 0; mi < 4; ++mi) {
            int r = wm * 64 + mi * 16 + g;
            uint32_t al0 = *(const uint32_t*)(sAlo + sw_off(r,     kb0));
            uint32_t al1 = *(const uint32_t*)(sAlo + sw_off(r + 8, kb0));
            uint32_t al2 = *(const uint32_t*)(sAlo + sw_off(r,     kb0 + 16));
            uint32_t al3 = *(const uint32_t*)(sAlo + sw_off(r + 8, kb0 + 16));
            #pragma unroll
            for (int ni = 0; ni < 4; ++ni)
                mma16816(acc[mi][ni], al0, al1, al2, al3, fr.bh[ni][0], fr.bh[ni][1]);
        }
    }
}

// ---------------------------------------------------------------------------
// Stage A: U[b][j][d] = sum_{w,c} k[b][j+w-1][c] * Wop[d][w*CH+c]
// ---------------------------------------------------------------------------
__global__ __launch_bounds__(256) void gemmA_mma() {
    __shared__ __align__(16) uint8_t sAhi[TILE_BYTES], sAlo[TILE_BYTES];
    __shared__ __align__(16) uint8_t sBhi[TILE_BYTES], sBlo[TILE_BYTES];

    const int b  = blockIdx.z;
    const int jt = blockIdx.y * 128;
    const int dt = blockIdx.x * 128;
    const int tid = threadIdx.x, lane = tid & 31, wid = tid >> 5;
    const int wm = wid >> 2, wn = wid & 3;
    const int g = lane >> 2, t = lane & 3;

    float acc[4][4][4];
    #pragma unroll
    for (int a = 0; a < 4; ++a)
        #pragma unroll
        for (int bq = 0; bq < 4; ++bq)
            #pragma unroll
            for (int c = 0; c < 4; ++c) acc[a][bq][c] = 0.f;

    for (int ch = 0; ch < 48; ++ch) {
        const int w  = ch >> 4;
        const int c0 = (ch & 15) * 32;
        #pragma unroll
        for (int u = 0; u < 2; ++u) {
            int f = tid + u * 256;
            int row = f >> 2, col8 = f & 3;
            uint32_t so = sw_off(row, col8 * 16);
            int jg = jt + row + w - 1;
            uint4 vh = make_uint4(0, 0, 0, 0), vl = make_uint4(0, 0, 0, 0);
            if (jg >= 0 && jg < LK) {
                size_t gi = ((size_t)b * LK + jg) * CH + c0 + col8 * 8;
                vh = *reinterpret_cast<const uint4*>(g_khi + gi);
                vl = *reinterpret_cast<const uint4*>(g_klo + gi);
            }
            *reinterpret_cast<uint4*>(sAhi + so) = vh;
            *reinterpret_cast<uint4*>(sAlo + so) = vl;
            size_t wi = (size_t)(dt + row) * KTOT + w * CH + c0 + col8 * 8;
            *reinterpret_cast<uint4*>(sBhi + so) = *reinterpret_cast<const uint4*>(g_Whi + wi);
            *reinterpret_cast<uint4*>(sBlo + so) = *reinterpret_cast<const uint4*>(g_Wlo + wi);
        }
        __syncthreads();
        gemm_chunk(sAhi, sAlo, sBhi, sBlo, wm, wn, g, t, acc);
        __syncthreads();
    }

    // epilogue: split fp32 -> bf16 hi/lo, store U (register packing only)
    #pragma unroll
    for (int mi = 0; mi < 4; ++mi) {
        #pragma unroll
        for (int ni = 0; ni < 4; ++ni) {
            int j0 = jt + wm * 64 + mi * 16 + g;
            int d0 = dt + wn * 32 + ni * 8 + 2 * t;
            #pragma unroll
            for (int rr = 0; rr < 2; ++rr) {
                float v0 = acc[mi][ni][rr * 2 + 0];
                float v1 = acc[mi][ni][rr * 2 + 1];
                float l0, l1;
                uint32_t hp = pack_hi(v0, v1, l0, l1);
                uint32_t lp = pack_bf(l0, l1);
                size_t o = ((size_t)b * LK + (j0 + rr * 8)) * DIM + d0;
                *reinterpret_cast<uint32_t*>(g_Uhi + o) = hp;
                *reinterpret_cast<uint32_t*>(g_Ulo + o) = lp;
            }
        }
    }
}

// ---------------------------------------------------------------------------
// Stage B: out[b][i][j] = q[b][i][:] . U[b][j][:] + qb[b,i] + bbj[b,j] + bias_b
// ---------------------------------------------------------------------------
__global__ __launch_bounds__(256) void gemmB_mma(const float* __restrict__ biasb,
                                                 float* __restrict__ out) {
    __shared__ __align__(16) uint8_t sAhi[TILE_BYTES], sAlo[TILE_BYTES];
    __shared__ __align__(16) uint8_t sBhi[TILE_BYTES], sBlo[TILE_BYTES];

    const int b  = blockIdx.z;
    const int it = blockIdx.y * 128;
    const int jt = blockIdx.x * 128;
    const int tid = threadIdx.x, lane = tid & 31, wid = tid >> 5;
    const int wm = wid >> 2, wn = wid & 3;
    const int g = lane >> 2, t = lane & 3;

    float acc[4][4][4];
    #pragma unroll
    for (int a = 0; a < 4; ++a)
        #pragma unroll
        for (int bq = 0; bq < 4; ++bq)
            #pragma unroll
            for (int c = 0; c < 4; ++c) acc[a][bq][c] = 0.f;

    for (int ch = 0; ch < 16; ++ch) {
        const int kt = ch * 32;
        #pragma unroll
        for (int u = 0; u < 2; ++u) {
            int f = tid + u * 256;
            int row = f >> 2, col8 = f & 3;
            uint32_t so = sw_off(row, col8 * 16);
            size_t qi = ((size_t)b * LQ + it + row) * DIM + kt + col8 * 8;
            *reinterpret_cast<uint4*>(sAhi + so) = *reinterpret_cast<const uint4*>(g_qhi + qi);
            *reinterpret_cast<uint4*>(sAlo + so) = *reinterpret_cast<const uint4*>(g_qlo + qi);
            size_t ui = ((size_t)b * LK + jt + row) * DIM + kt + col8 * 8;
            *reinterpret_cast<uint4*>(sBhi + so) = *reinterpret_cast<const uint4*>(g_Uhi + ui);
            *reinterpret_cast<uint4*>(sBlo + so) = *reinterpret_cast<const uint4*>(g_Ulo + ui);
        }
        __syncthreads();
        gemm_chunk(sAhi, sAlo, sBhi, sBlo, wm, wn, g, t, acc);
        __syncthreads();
    }

    const float bB = biasb[0];
    #pragma unroll
    for (int mi = 0; mi < 4; ++mi) {
        int i0 = it + wm * 64 + mi * 16 + g;
        float cb0 = g_qb[b * LQ + i0] + bB;
        float cb1 = g_qb[b * LQ + i0 + 8] + bB;
        #pragma unroll
        for (int ni = 0; ni < 4; ++ni) {
            int j0 = jt + wn * 32 + ni * 8 + 2 * t;
            float bb0 = g_bbj[b * LK + j0];
            float bb1 = g_bbj[b * LK + j0 + 1];
            float2 r0 = make_float2(acc[mi][ni][0] + cb0 + bb0,
                                    acc[mi][ni][1] + cb0 + bb1);
            float2 r1 = make_float2(acc[mi][ni][2] + cb1 + bb0,
                                    acc[mi][ni][3] + cb1 + bb1);
            *reinterpret_cast<float2*>(out + ((size_t)b * LQ + i0) * LK + j0)       = r0;
            *reinterpret_cast<float2*>(out + ((size_t)b * LQ + i0 + 8) * LK + j0)   = r1;
        }
    }
}

// ---------------------------------------------------------------------------
extern "C" void kernel_launch(void* const* d_in, const int* in_sizes, int n_in,
                              void* d_out, int out_size) {
    const float* q     = (const float*)d_in[0];   // (8,1024,512)
    const float* k     = (const float*)d_in[1];   // (8,1024,512)
    const float* W     = (const float*)d_in[2];   // (512,1536)
    const float* bk    = (const float*)d_in[3];   // (1536,)
    const float* Wb    = (const float*)d_in[4];   // (512,1)
    const float* bb    = (const float*)d_in[5];   // (1,)
    const float* biasb = (const float*)d_in[6];   // (1,)
    float* out = (float*)d_out;                   // (8,1024,1024)

    // bf16 hi/lo conversions (globals referenced inside the kernels only)
    int n4 = BATCH * LQ * DIM / 4;
    split_q_kernel<<<(n4 + 255) / 256, 256>>>(q);
    split_k_kernel<<<(n4 + 255) / 256, 256>>>(k);
    wsplit_kernel<<<(DIM * KTOT + 255) / 256, 256>>>(W);

    qb_kernel<<<(BATCH * LQ) / 8, 256>>>(q, Wb, bb);
    bbj_kernel<<<(BATCH * LK) / 8, 256>>>(k, bk);

    dim3 gA(DIM / 128, LK / 128, BATCH);          // (4, 8, 8)
    gemmA_mma<<<gA, 256>>>();

    dim3 gB(LK / 128, LQ / 128, BATCH);           // (8, 8, 8)
    gemmB_mma<<<gB, 256>>>(biasb, out);
}

// round 7
// speedup vs baseline: 2.6160x; 2.0749x over previous
#include <cuda_runtime.h>
#include <cuda_bf16.h>
#include <cstdint>

// Problem shapes (fixed by the dataset)
#define BATCH 8
#define LQ    1024
#define LK    1024
#define DIM   512
#define CH    512
#define KTOT  1536   // 3*CH

// ---------------------------------------------------------------------------
// Scratch (device globals — allocation-free). Referenced ONLY from device code
// (host-side &g_xxx yields the shadow symbol: the round-3/4 bug).
// ---------------------------------------------------------------------------
__device__ __nv_bfloat16 g_qhi[BATCH * LQ * DIM];
__device__ __nv_bfloat16 g_qlo[BATCH * LQ * DIM];
__device__ __nv_bfloat16 g_khi[BATCH * LK * CH];
__device__ __nv_bfloat16 g_klo[BATCH * LK * CH];
__device__ __nv_bfloat16 g_Whi[DIM * KTOT];      // Wop[d][w*CH+c] = W[d, c*3+w]
__device__ __nv_bfloat16 g_Wlo[DIM * KTOT];
__device__ __nv_bfloat16 g_Uhi[BATCH * LK * DIM];
__device__ __nv_bfloat16 g_Ulo[BATCH * LK * DIM];
__device__ float g_bbj[BATCH * LK];
__device__ float g_qb[BATCH * LQ];

// ---------------------------------------------------------------------------
// PTX helpers
// ---------------------------------------------------------------------------
__device__ __forceinline__ void mma16816(float* c,
                                         uint32_t a0, uint32_t a1, uint32_t a2, uint32_t a3,
                                         uint32_t b0, uint32_t b1) {
    asm volatile(
        "mma.sync.aligned.m16n8k16.row.col.f32.bf16.bf16.f32 "
        "{%0,%1,%2,%3}, {%4,%5,%6,%7}, {%8,%9}, {%0,%1,%2,%3};"
        : "+f"(c[0]), "+f"(c[1]), "+f"(c[2]), "+f"(c[3])
        : "r"(a0), "r"(a1), "r"(a2), "r"(a3), "r"(b0), "r"(b1));
}

__device__ __forceinline__ void ldm4(uint32_t& r0, uint32_t& r1, uint32_t& r2, uint32_t& r3,
                                     uint32_t a) {
    asm volatile("ldmatrix.sync.aligned.m8n8.x4.shared.b16 {%0,%1,%2,%3}, [%4];"
                 : "=r"(r0), "=r"(r1), "=r"(r2), "=r"(r3) : "r"(a));
}

__device__ __forceinline__ uint32_t smem_u32(const void* p) {
    uint32_t a;
    asm("{ .reg .u64 t; cvta.to.shared.u64 t, %1; cvt.u32.u64 %0, t; }" : "=r"(a) : "l"(p));
    return a;
}

__device__ __forceinline__ void cpa16(uint32_t dst, const void* src, int srcsz) {
    asm volatile("cp.async.cg.shared.global [%0], [%1], 16, %2;"
                 :: "r"(dst), "l"(src), "r"(srcsz) : "memory");
}
#define CP_COMMIT() asm volatile("cp.async.commit_group;" ::: "memory")
#define CP_WAIT0()  asm volatile("cp.async.wait_group 0;" ::: "memory")
#define CP_WAIT1()  asm volatile("cp.async.wait_group 1;" ::: "memory")

// smem tile: 128 rows x 64 bytes (32 bf16), XOR-swizzled:
//   phys = row*64 + (kb ^ (((row>>1)&3)<<4))
__device__ __forceinline__ uint32_t sw_off(int row, int kb) {
    return (uint32_t)(row * 64 + (kb ^ (((row >> 1) & 3) << 4)));
}

// Pack two floats into one u32 of bf16 hi parts; residuals out (register ops).
__device__ __forceinline__ uint32_t pack_hi(float a, float b, float& ra, float& rb) {
    __nv_bfloat16 ha = __float2bfloat16(a);
    __nv_bfloat16 hb = __float2bfloat16(b);
    ra = a - __bfloat162float(ha);
    rb = b - __bfloat162float(hb);
    return (uint32_t)__bfloat16_as_ushort(ha) |
           ((uint32_t)__bfloat16_as_ushort(hb) << 16);
}
__device__ __forceinline__ uint32_t pack_bf(float a, float b) {
    return (uint32_t)__bfloat16_as_ushort(__float2bfloat16(a)) |
           ((uint32_t)__bfloat16_as_ushort(__float2bfloat16(b)) << 16);
}

// ---------------------------------------------------------------------------
// Preamble kernels (unchanged from passing round)
// ---------------------------------------------------------------------------
__device__ __forceinline__ void split_body(const float* __restrict__ s,
                                           __nv_bfloat16* hi, __nv_bfloat16* lo,
                                           int i) {
    float4 v = reinterpret_cast<const float4*>(s)[i];
    float rx, ry, rz, rw;
    uint32_t h01 = pack_hi(v.x, v.y, rx, ry);
    uint32_t h23 = pack_hi(v.z, v.w, rz, rw);
    reinterpret_cast<uint2*>(hi)[i] = make_uint2(h01, h23);
    reinterpret_cast<uint2*>(lo)[i] = make_uint2(pack_bf(rx, ry), pack_bf(rz, rw));
}

__global__ void split_q_kernel(const float* __restrict__ s) {
    int i = blockIdx.x * blockDim.x + threadIdx.x;
    if (i < BATCH * LQ * DIM / 4) split_body(s, g_qhi, g_qlo, i);
}
__global__ void split_k_kernel(const float* __restrict__ s) {
    int i = blockIdx.x * blockDim.x + threadIdx.x;
    if (i < BATCH * LK * CH / 4) split_body(s, g_khi, g_klo, i);
}

__global__ void wsplit_kernel(const float* __restrict__ W) {
    int idx = blockIdx.x * blockDim.x + threadIdx.x;
    if (idx >= DIM * KTOT) return;
    int d  = idx / KTOT;
    int wc = idx % KTOT;
    int w  = wc / CH;
    int c  = wc % CH;
    float f = W[d * KTOT + c * 3 + w];
    __nv_bfloat16 h = __float2bfloat16(f);
    g_Whi[idx] = h;
    g_Wlo[idx] = __float2bfloat16(f - __bfloat162float(h));
}

__global__ void qb_kernel(const float* __restrict__ q,
                          const float* __restrict__ Wb,
                          const float* __restrict__ bb) {
    int warp = (blockIdx.x * blockDim.x + threadIdx.x) >> 5;
    int lane = threadIdx.x & 31;
    if (warp >= BATCH * LQ) return;
    const float* qr = q + (size_t)warp * DIM;
    float s = 0.f;
    #pragma unroll 4
    for (int d = lane; d < DIM; d += 32) s += qr[d] * Wb[d];
    #pragma unroll
    for (int o = 16; o; o >>= 1) s += __shfl_down_sync(0xFFFFFFFFu, s, o);
    if (lane == 0) g_qb[warp] = s + bb[0];
}

__global__ void bbj_kernel(const float* __restrict__ K,
                           const float* __restrict__ bk) {
    int warp = (blockIdx.x * blockDim.x + threadIdx.x) >> 5;
    int lane = threadIdx.x & 31;
    if (warp >= BATCH * LK) return;
    int b = warp / LK;
    int j = warp % LK;
    float s = 0.f;
    #pragma unroll
    for (int w = 0; w < 3; ++w) {
        int r = j + w - 1;
        if (r < 0 || r >= LK) continue;
        const float* kr = K + ((size_t)b * LK + r) * CH;
        #pragma unroll 4
        for (int c = lane; c < CH; c += 32) s += bk[c * 3 + w] * kr[c];
    }
    #pragma unroll
    for (int o = 16; o; o >>= 1) s += __shfl_down_sync(0xFFFFFFFFu, s, o);
    if (lane == 0) g_bbj[warp] = s;
}

// ---------------------------------------------------------------------------
// GEMM core: CTA 128x128, BK=32, 8 warps, warp tile 64x32.
// 2-stage cp.async pipeline; ldmatrix.x4 fragments; split-bf16 3-product.
// smem stage layout: Ahi@0, Alo@8K, Bhi@16K, Blo@24K; two stages = 64KB.
// ---------------------------------------------------------------------------
#define OFF_AL 8192
#define OFF_BH 16384
#define OFF_BL 24576
#define STAGE_BYTES 32768
#define SMEM_TOTAL  (2 * STAGE_BYTES)

struct LdmCtx {
    int tA[4], xA[4];   // per-mi: rowA*64, xor term
    int tB[2], xB[2];   // per-nii (pair of ni)
    int kkA, kkB;       // per-lane k-half byte offsets
};

__device__ __forceinline__ LdmCtx make_ctx(int lane, int wm, int wn) {
    LdmCtx c;
    #pragma unroll
    for (int mi = 0; mi < 4; ++mi) {
        int r = wm * 64 + mi * 16 + ((lane >> 3) & 1) * 8 + (lane & 7);
        c.tA[mi] = r * 64;
        c.xA[mi] = ((r >> 1) & 3) << 4;
    }
    #pragma unroll
    for (int nii = 0; nii < 2; ++nii) {
        int r = wn * 32 + nii * 16 + ((lane >> 4) & 1) * 8 + (lane & 7);
        c.tB[nii] = r * 64;
        c.xB[nii] = ((r >> 1) & 3) << 4;
    }
    c.kkA = (lane >> 4) * 16;          // A: matrices 2,3 take k+8 half
    c.kkB = ((lane >> 3) & 1) * 16;    // B: matrices 1,3 take k+8 half
    return c;
}

__device__ __forceinline__ void compute_chunk(uint32_t st, const LdmCtx& c,
                                              float acc[4][4][4]) {
    #pragma unroll
    for (int ks = 0; ks < 2; ++ks) {
        const int kbA = ks * 32 + c.kkA;
        const int kbB = ks * 32 + c.kkB;
        uint32_t adr[4];
        uint32_t ah[4][4], bh[2][4];
        #pragma unroll
        for (int mi = 0; mi < 4; ++mi) {
            adr[mi] = st + c.tA[mi] + (uint32_t)(kbA ^ c.xA[mi]);
            ldm4(ah[mi][0], ah[mi][1], ah[mi][2], ah[mi][3], adr[mi]);
        }
        uint32_t bdr[2];
        #pragma unroll
        for (int nii = 0; nii < 2; ++nii) {
            bdr[nii] = st + OFF_BH + c.tB[nii] + (uint32_t)(kbB ^ c.xB[nii]);
            ldm4(bh[nii][0], bh[nii][1], bh[nii][2], bh[nii][3], bdr[nii]);
        }
        // pass 1: hi*hi
        #pragma unroll
        for (int mi = 0; mi < 4; ++mi)
            #pragma unroll
            for (int ni = 0; ni < 4; ++ni)
                mma16816(acc[mi][ni], ah[mi][0], ah[mi][1], ah[mi][2], ah[mi][3],
                         bh[ni >> 1][(ni & 1) * 2], bh[ni >> 1][(ni & 1) * 2 + 1]);
        // pass 2: hi*lo (reuse ah)
        #pragma unroll
        for (int nii = 0; nii < 2; ++nii) {
            uint32_t bl0, bl1, bl2, bl3;
            ldm4(bl0, bl1, bl2, bl3, bdr[nii] + (OFF_BL - OFF_BH));
            #pragma unroll
            for (int mi = 0; mi < 4; ++mi) {
                mma16816(acc[mi][nii * 2 + 0], ah[mi][0], ah[mi][1], ah[mi][2], ah[mi][3], bl0, bl1);
                mma16816(acc[mi][nii * 2 + 1], ah[mi][0], ah[mi][1], ah[mi][2], ah[mi][3], bl2, bl3);
            }
        }
        // pass 3: lo*hi (reuse bh)
        #pragma unroll
        for (int mi = 0; mi < 4; ++mi) {
            uint32_t al0, al1, al2, al3;
            ldm4(al0, al1, al2, al3, adr[mi] + OFF_AL);
            #pragma unroll
            for (int ni = 0; ni < 4; ++ni)
                mma16816(acc[mi][ni], al0, al1, al2, al3,
                         bh[ni >> 1][(ni & 1) * 2], bh[ni >> 1][(ni & 1) * 2 + 1]);
        }
    }
}

// ---------------------------------------------------------------------------
// Stage A: U[b][j][d] = sum_{w,c} k[b][j+w-1][c] * Wop[d][w*CH+c]
// ---------------------------------------------------------------------------
__device__ __forceinline__ void loadA_stage(uint32_t sbase, int b, int jt, int dt,
                                            int ch, int tid) {
    const int w  = ch >> 4;
    const int c0 = (ch & 15) * 32;
    #pragma unroll
    for (int u = 0; u < 2; ++u) {
        int f = tid + u * 256;             // 0..511
        int row = f >> 2, c16 = f & 3;
        uint32_t so = sw_off(row, c16 * 16);
        int jg = jt + row + w - 1;
        int ok = (jg >= 0 && jg < LK) ? 16 : 0;
        int jc = (jg >= 0 && jg < LK) ? jg : 0;
        size_t gi = ((size_t)b * LK + jc) * CH + c0 + c16 * 8;
        cpa16(sbase + so,          g_khi + gi, ok);
        cpa16(sbase + OFF_AL + so, g_klo + gi, ok);
        size_t wi = (size_t)(dt + row) * KTOT + w * CH + c0 + c16 * 8;
        cpa16(sbase + OFF_BH + so, g_Whi + wi, 16);
        cpa16(sbase + OFF_BL + so, g_Wlo + wi, 16);
    }
}

__global__ __launch_bounds__(256) void gemmA_mma() {
    extern __shared__ __align__(16) uint8_t smem[];
    const int b  = blockIdx.z;
    const int jt = blockIdx.y * 128;
    const int dt = blockIdx.x * 128;
    const int tid = threadIdx.x, lane = tid & 31, wid = tid >> 5;
    const int wm = wid >> 2, wn = wid & 3;
    const int g = lane >> 2, t = lane & 3;
    const uint32_t sb = smem_u32(smem);
    const LdmCtx ctx = make_ctx(lane, wm, wn);

    float acc[4][4][4];
    #pragma unroll
    for (int a = 0; a < 4; ++a)
        #pragma unroll
        for (int bq = 0; bq < 4; ++bq)
            #pragma unroll
            for (int c = 0; c < 4; ++c) acc[a][bq][c] = 0.f;

    loadA_stage(sb, b, jt, dt, 0, tid);
    CP_COMMIT();
    for (int ch = 0; ch < 48; ++ch) {
        uint32_t cur = sb + (uint32_t)(ch & 1) * STAGE_BYTES;
        if (ch + 1 < 48) {
            loadA_stage(sb + (uint32_t)((ch + 1) & 1) * STAGE_BYTES, b, jt, dt, ch + 1, tid);
            CP_COMMIT();
            CP_WAIT1();
        } else {
            CP_WAIT0();
        }
        __syncthreads();
        compute_chunk(cur, ctx, acc);
        __syncthreads();
    }

    // epilogue: split fp32 -> bf16 hi/lo, store U (register packing only)
    #pragma unroll
    for (int mi = 0; mi < 4; ++mi) {
        #pragma unroll
        for (int ni = 0; ni < 4; ++ni) {
            int j0 = jt + wm * 64 + mi * 16 + g;
            int d0 = dt + wn * 32 + ni * 8 + 2 * t;
            #pragma unroll
            for (int rr = 0; rr < 2; ++rr) {
                float v0 = acc[mi][ni][rr * 2 + 0];
                float v1 = acc[mi][ni][rr * 2 + 1];
                float l0, l1;
                uint32_t hp = pack_hi(v0, v1, l0, l1);
                uint32_t lp = pack_bf(l0, l1);
                size_t o = ((size_t)b * LK + (j0 + rr * 8)) * DIM + d0;
                *reinterpret_cast<uint32_t*>(g_Uhi + o) = hp;
                *reinterpret_cast<uint32_t*>(g_Ulo + o) = lp;
            }
        }
    }
}

// ---------------------------------------------------------------------------
// Stage B: out[b][i][j] = q[b][i][:] . U[b][j][:] + qb[b,i] + bbj[b,j] + bias_b
// ---------------------------------------------------------------------------
__device__ __forceinline__ void loadB_stage(uint32_t sbase, int b, int it, int jt,
                                            int ch, int tid) {
    const int kt = ch * 32;
    #pragma unroll
    for (int u = 0; u < 2; ++u) {
        int f = tid + u * 256;
        int row = f >> 2, c16 = f & 3;
        uint32_t so = sw_off(row, c16 * 16);
        size_t qi = ((size_t)b * LQ + it + row) * DIM + kt + c16 * 8;
        cpa16(sbase + so,          g_qhi + qi, 16);
        cpa16(sbase + OFF_AL + so, g_qlo + qi, 16);
        size_t ui = ((size_t)b * LK + jt + row) * DIM + kt + c16 * 8;
        cpa16(sbase + OFF_BH + so, g_Uhi + ui, 16);
        cpa16(sbase + OFF_BL + so, g_Ulo + ui, 16);
    }
}

__global__ __launch_bounds__(256) void gemmB_mma(const float* __restrict__ biasb,
                                                 float* __restrict__ out) {
    extern __shared__ __align__(16) uint8_t smem[];
    const int b  = blockIdx.z;
    const int it = blockIdx.y * 128;
    const int jt = blockIdx.x * 128;
    const int tid = threadIdx.x, lane = tid & 31, wid = tid >> 5;
    const int wm = wid >> 2, wn = wid & 3;
    const int g = lane >> 2, t = lane & 3;
    const uint32_t sb = smem_u32(smem);
    const LdmCtx ctx = make_ctx(lane, wm, wn);

    float acc[4][4][4];
    #pragma unroll
    for (int a = 0; a < 4; ++a)
        #pragma unroll
        for (int bq = 0; bq < 4; ++bq)
            #pragma unroll
            for (int c = 0; c < 4; ++c) acc[a][bq][c] = 0.f;

    loadB_stage(sb, b, it, jt, 0, tid);
    CP_COMMIT();
    for (int ch = 0; ch < 16; ++ch) {
        uint32_t cur = sb + (uint32_t)(ch & 1) * STAGE_BYTES;
        if (ch + 1 < 16) {
            loadB_stage(sb + (uint32_t)((ch + 1) & 1) * STAGE_BYTES, b, it, jt, ch + 1, tid);
            CP_COMMIT();
            CP_WAIT1();
        } else {
            CP_WAIT0();
        }
        __syncthreads();
        compute_chunk(cur, ctx, acc);
        __syncthreads();
    }

    const float bB = biasb[0];
    #pragma unroll
    for (int mi = 0; mi < 4; ++mi) {
        int i0 = it + wm * 64 + mi * 16 + g;
        float cb0 = g_qb[b * LQ + i0] + bB;
        float cb1 = g_qb[b * LQ + i0 + 8] + bB;
        #pragma unroll
        for (int ni = 0; ni < 4; ++ni) {
            int j0 = jt + wn * 32 + ni * 8 + 2 * t;
            float bb0 = g_bbj[b * LK + j0];
            float bb1 = g_bbj[b * LK + j0 + 1];
            float2 r0 = make_float2(acc[mi][ni][0] + cb0 + bb0,
                                    acc[mi][ni][1] + cb0 + bb1);
            float2 r1 = make_float2(acc[mi][ni][2] + cb1 + bb0,
                                    acc[mi][ni][3] + cb1 + bb1);
            *reinterpret_cast<float2*>(out + ((size_t)b * LQ + i0) * LK + j0)     = r0;
            *reinterpret_cast<float2*>(out + ((size_t)b * LQ + i0 + 8) * LK + j0) = r1;
        }
    }
}

// ---------------------------------------------------------------------------
extern "C" void kernel_launch(void* const* d_in, const int* in_sizes, int n_in,
                              void* d_out, int out_size) {
    const float* q     = (const float*)d_in[0];   // (8,1024,512)
    const float* k     = (const float*)d_in[1];   // (8,1024,512)
    const float* W     = (const float*)d_in[2];   // (512,1536)
    const float* bk    = (const float*)d_in[3];   // (1536,)
    const float* Wb    = (const float*)d_in[4];   // (512,1)
    const float* bb    = (const float*)d_in[5];   // (1,)
    const float* biasb = (const float*)d_in[6];   // (1,)
    float* out = (float*)d_out;                   // (8,1024,1024)

    // idempotent, deterministic — no static guard
    cudaFuncSetAttribute(gemmA_mma, cudaFuncAttributeMaxDynamicSharedMemorySize, SMEM_TOTAL);
    cudaFuncSetAttribute(gemmB_mma, cudaFuncAttributeMaxDynamicSharedMemorySize, SMEM_TOTAL);

    int n4 = BATCH * LQ * DIM / 4;
    split_q_kernel<<<(n4 + 255) / 256, 256>>>(q);
    split_k_kernel<<<(n4 + 255) / 256, 256>>>(k);
    wsplit_kernel<<<(DIM * KTOT + 255) / 256, 256>>>(W);

    qb_kernel<<<(BATCH * LQ) / 8, 256>>>(q, Wb, bb);
    bbj_kernel<<<(BATCH * LK) / 8, 256>>>(k, bk);

    dim3 gA(DIM / 128, LK / 128, BATCH);          // (4, 8, 8)
    gemmA_mma<<<gA, 256, SMEM_TOTAL>>>();

    dim3 gB(LK / 128, LQ / 128, BATCH);           // (8, 8, 8)
    gemmB_mma<<<gB, 256, SMEM_TOTAL>>>(biasb, out);
}

// round 8
// speedup vs baseline: 3.0822x; 1.1782x over previous
#include <cuda_runtime.h>
#include <cuda_bf16.h>
#include <cstdint>

// Problem shapes (fixed by the dataset)
#define BATCH 8
#define LQ    1024
#define LK    1024
#define DIM   512
#define CH    512
#define KTOT  1536   // 3*CH

// ---------------------------------------------------------------------------
// Scratch (device globals — allocation-free). Referenced ONLY from device code
// (host-side &g_xxx yields the shadow symbol: the round-3/4 bug).
// ---------------------------------------------------------------------------
__device__ __nv_bfloat16 g_qhi[BATCH * LQ * DIM];
__device__ __nv_bfloat16 g_qlo[BATCH * LQ * DIM];
__device__ __nv_bfloat16 g_khi[BATCH * LK * CH];
__device__ __nv_bfloat16 g_klo[BATCH * LK * CH];
__device__ __nv_bfloat16 g_Whi[DIM * KTOT];      // Wop[d][w*CH+c] = W[d, c*3+w]
__device__ __nv_bfloat16 g_Wlo[DIM * KTOT];
__device__ __nv_bfloat16 g_Uhi[BATCH * LK * DIM];
__device__ __nv_bfloat16 g_Ulo[BATCH * LK * DIM];
__device__ float g_bbj[BATCH * LK];
__device__ float g_qb[BATCH * LQ];
__device__ float g_t0[BATCH * LK];               // per-row dots for bbj conv
__device__ float g_t1[BATCH * LK];
__device__ float g_t2[BATCH * LK];

// ---------------------------------------------------------------------------
// PTX helpers
// ---------------------------------------------------------------------------
__device__ __forceinline__ void mma16816(float* c,
                                         uint32_t a0, uint32_t a1, uint32_t a2, uint32_t a3,
                                         uint32_t b0, uint32_t b1) {
    asm volatile(
        "mma.sync.aligned.m16n8k16.row.col.f32.bf16.bf16.f32 "
        "{%0,%1,%2,%3}, {%4,%5,%6,%7}, {%8,%9}, {%0,%1,%2,%3};"
        : "+f"(c[0]), "+f"(c[1]), "+f"(c[2]), "+f"(c[3])
        : "r"(a0), "r"(a1), "r"(a2), "r"(a3), "r"(b0), "r"(b1));
}

__device__ __forceinline__ void ldm4(uint32_t& r0, uint32_t& r1, uint32_t& r2, uint32_t& r3,
                                     uint32_t a) {
    asm volatile("ldmatrix.sync.aligned.m8n8.x4.shared.b16 {%0,%1,%2,%3}, [%4];"
                 : "=r"(r0), "=r"(r1), "=r"(r2), "=r"(r3) : "r"(a));
}

__device__ __forceinline__ uint32_t smem_u32(const void* p) {
    uint32_t a;
    asm("{ .reg .u64 t; cvta.to.shared.u64 t, %1; cvt.u32.u64 %0, t; }" : "=r"(a) : "l"(p));
    return a;
}

__device__ __forceinline__ void cpa16(uint32_t dst, const void* src, int srcsz) {
    asm volatile("cp.async.cg.shared.global [%0], [%1], 16, %2;"
                 :: "r"(dst), "l"(src), "r"(srcsz) : "memory");
}
#define CP_COMMIT() asm volatile("cp.async.commit_group;" ::: "memory")
#define CP_WAIT0()  asm volatile("cp.async.wait_group 0;" ::: "memory")
#define CP_WAIT1()  asm volatile("cp.async.wait_group 1;" ::: "memory")

// smem tile: 128 rows x 64 bytes (32 bf16), XOR-swizzled:
//   phys = row*64 + (kb ^ (((row>>1)&3)<<4))
__device__ __forceinline__ uint32_t sw_off(int row, int kb) {
    return (uint32_t)(row * 64 + (kb ^ (((row >> 1) & 3) << 4)));
}

// Pack two floats into one u32 of bf16 hi parts; residuals out (register ops).
__device__ __forceinline__ uint32_t pack_hi(float a, float b, float& ra, float& rb) {
    __nv_bfloat16 ha = __float2bfloat16(a);
    __nv_bfloat16 hb = __float2bfloat16(b);
    ra = a - __bfloat162float(ha);
    rb = b - __bfloat162float(hb);
    return (uint32_t)__bfloat16_as_ushort(ha) |
           ((uint32_t)__bfloat16_as_ushort(hb) << 16);
}
__device__ __forceinline__ uint32_t pack_bf(float a, float b) {
    return (uint32_t)__bfloat16_as_ushort(__float2bfloat16(a)) |
           ((uint32_t)__bfloat16_as_ushort(__float2bfloat16(b)) << 16);
}

// ---------------------------------------------------------------------------
// Fused preamble: warp per row.
// fused_q: split q -> hi/lo AND qb[row] = q[row]·Wb + bb   (q read once)
// ---------------------------------------------------------------------------
__global__ void fused_q_kernel(const float* __restrict__ q,
                               const float* __restrict__ Wb,
                               const float* __restrict__ bb) {
    int gw   = (blockIdx.x * blockDim.x + threadIdx.x) >> 5;   // 0..8191
    int lane = threadIdx.x & 31;
    if (gw >= BATCH * LQ) return;
    const float4* qr  = reinterpret_cast<const float4*>(q) + (size_t)gw * 128;
    const float4* wb4 = reinterpret_cast<const float4*>(Wb);
    float s = 0.f;
    #pragma unroll
    for (int v = 0; v < 4; ++v) {
        int idx = lane + 32 * v;
        float4 x = qr[idx];
        float4 wv = wb4[idx];
        s += x.x * wv.x + x.y * wv.y + x.z * wv.z + x.w * wv.w;
        float rx, ry, rz, rw;
        uint32_t h01 = pack_hi(x.x, x.y, rx, ry);
        uint32_t h23 = pack_hi(x.z, x.w, rz, rw);
        size_t o = (size_t)gw * 128 + idx;
        reinterpret_cast<uint2*>(g_qhi)[o] = make_uint2(h01, h23);
        reinterpret_cast<uint2*>(g_qlo)[o] = make_uint2(pack_bf(rx, ry), pack_bf(rz, rw));
    }
    #pragma unroll
    for (int o = 16; o; o >>= 1) s += __shfl_down_sync(0xFFFFFFFFu, s, o);
    if (lane == 0) g_qb[gw] = s + bb[0];
}

// fused_k: split k -> hi/lo AND t_w[row] = bk_w · k[row] for w=0,1,2
// (k read once; bbj assembled by combine kernel: bbj[j]=t0[j-1]+t1[j]+t2[j+1])
__global__ void fused_k_kernel(const float* __restrict__ k,
                               const float* __restrict__ bk) {
    int gw   = (blockIdx.x * blockDim.x + threadIdx.x) >> 5;
    int lane = threadIdx.x & 31;
    if (gw >= BATCH * LK) return;
    const float4* kr  = reinterpret_cast<const float4*>(k) + (size_t)gw * 128;
    const float4* bk4 = reinterpret_cast<const float4*>(bk);
    float t0 = 0.f, t1 = 0.f, t2 = 0.f;
    #pragma unroll
    for (int v = 0; v < 4; ++v) {
        int idx = lane + 32 * v;          // float4 slot; c0 = 4*idx
        float4 x = kr[idx];
        // bk[3c+w] for c in {4idx..4idx+3}: 12 contiguous floats = 3 float4s
        float4 f0 = bk4[3 * idx + 0];
        float4 f1 = bk4[3 * idx + 1];
        float4 f2 = bk4[3 * idx + 2];
        t0 += x.x * f0.x + x.y * f0.w + x.z * f1.z + x.w * f2.y;
        t1 += x.x * f0.y + x.y * f1.x + x.z * f1.w + x.w * f2.z;
        t2 += x.x * f0.z + x.y * f1.y + x.z * f2.x + x.w * f2.w;
        float rx, ry, rz, rw;
        uint32_t h01 = pack_hi(x.x, x.y, rx, ry);
        uint32_t h23 = pack_hi(x.z, x.w, rz, rw);
        size_t o = (size_t)gw * 128 + idx;
        reinterpret_cast<uint2*>(g_khi)[o] = make_uint2(h01, h23);
        reinterpret_cast<uint2*>(g_klo)[o] = make_uint2(pack_bf(rx, ry), pack_bf(rz, rw));
    }
    #pragma unroll
    for (int o = 16; o; o >>= 1) {
        t0 += __shfl_down_sync(0xFFFFFFFFu, t0, o);
        t1 += __shfl_down_sync(0xFFFFFFFFu, t1, o);
        t2 += __shfl_down_sync(0xFFFFFFFFu, t2, o);
    }
    if (lane == 0) { g_t0[gw] = t0; g_t1[gw] = t1; g_t2[gw] = t2; }
}

__global__ void combine_bbj_kernel() {
    int idx = blockIdx.x * blockDim.x + threadIdx.x;
    if (idx >= BATCH * LK) return;
    int j = idx % LK;
    float s = g_t1[idx];
    if (j > 0)      s += g_t0[idx - 1];
    if (j < LK - 1) s += g_t2[idx + 1];
    g_bbj[idx] = s;
}

// W repack + split: Wop[d][w*CH+c] = W[d, c*3+w]
__global__ void wsplit_kernel(const float* __restrict__ W) {
    int idx = blockIdx.x * blockDim.x + threadIdx.x;
    if (idx >= DIM * KTOT) return;
    int d  = idx / KTOT;
    int wc = idx % KTOT;
    int w  = wc / CH;
    int c  = wc % CH;
    float f = W[d * KTOT + c * 3 + w];
    __nv_bfloat16 h = __float2bfloat16(f);
    g_Whi[idx] = h;
    g_Wlo[idx] = __float2bfloat16(f - __bfloat162float(h));
}

// ---------------------------------------------------------------------------
// GEMM core: CTA 128x128, BK=32, 8 warps, warp tile 64x32.
// 3-stage cp.async ring (single __syncthreads per chunk); ldmatrix.x4;
// split-bf16 3-product. Stage: Ahi@0, Alo@8K, Bhi@16K, Blo@24K (32KB).
// __launch_bounds__(256,2): cap 128 regs -> 2 CTAs/SM (4 warps/SMSP).
// ---------------------------------------------------------------------------
#define OFF_AL 8192
#define OFF_BH 16384
#define OFF_BL 24576
#define STAGE_BYTES 32768
#define NSTAGE 3
#define SMEM_TOTAL  (NSTAGE * STAGE_BYTES)

struct LdmCtx {
    int tA[4], xA[4];   // per-mi: rowA*64, xor term
    int tB[2], xB[2];   // per-nii (pair of ni)
    int kkA, kkB;       // per-lane k-half byte offsets
};

__device__ __forceinline__ LdmCtx make_ctx(int lane, int wm, int wn) {
    LdmCtx c;
    #pragma unroll
    for (int mi = 0; mi < 4; ++mi) {
        int r = wm * 64 + mi * 16 + ((lane >> 3) & 1) * 8 + (lane & 7);
        c.tA[mi] = r * 64;
        c.xA[mi] = ((r >> 1) & 3) << 4;
    }
    #pragma unroll
    for (int nii = 0; nii < 2; ++nii) {
        int r = wn * 32 + nii * 16 + ((lane >> 4) & 1) * 8 + (lane & 7);
        c.tB[nii] = r * 64;
        c.xB[nii] = ((r >> 1) & 3) << 4;
    }
    c.kkA = (lane >> 4) * 16;          // A: matrices 2,3 take k+8 half
    c.kkB = ((lane >> 3) & 1) * 16;    // B: matrices 1,3 take k+8 half
    return c;
}

__device__ __forceinline__ void compute_chunk(uint32_t st, const LdmCtx& c,
                                              float acc[4][4][4]) {
    #pragma unroll
    for (int ks = 0; ks < 2; ++ks) {
        const int kbA = ks * 32 + c.kkA;
        const int kbB = ks * 32 + c.kkB;
        uint32_t adr[4];
        uint32_t ah[4][4], bh[2][4];
        #pragma unroll
        for (int mi = 0; mi < 4; ++mi) {
            adr[mi] = st + c.tA[mi] + (uint32_t)(kbA ^ c.xA[mi]);
            ldm4(ah[mi][0], ah[mi][1], ah[mi][2], ah[mi][3], adr[mi]);
        }
        uint32_t bdr[2];
        #pragma unroll
        for (int nii = 0; nii < 2; ++nii) {
            bdr[nii] = st + OFF_BH + c.tB[nii] + (uint32_t)(kbB ^ c.xB[nii]);
            ldm4(bh[nii][0], bh[nii][1], bh[nii][2], bh[nii][3], bdr[nii]);
        }
        // pass 1: hi*hi
        #pragma unroll
        for (int mi = 0; mi < 4; ++mi)
            #pragma unroll
            for (int ni = 0; ni < 4; ++ni)
                mma16816(acc[mi][ni], ah[mi][0], ah[mi][1], ah[mi][2], ah[mi][3],
                         bh[ni >> 1][(ni & 1) * 2], bh[ni >> 1][(ni & 1) * 2 + 1]);
        // pass 2: hi*lo (reuse ah)
        #pragma unroll
        for (int nii = 0; nii < 2; ++nii) {
            uint32_t bl0, bl1, bl2, bl3;
            ldm4(bl0, bl1, bl2, bl3, bdr[nii] + (OFF_BL - OFF_BH));
            #pragma unroll
            for (int mi = 0; mi < 4; ++mi) {
                mma16816(acc[mi][nii * 2 + 0], ah[mi][0], ah[mi][1], ah[mi][2], ah[mi][3], bl0, bl1);
                mma16816(acc[mi][nii * 2 + 1], ah[mi][0], ah[mi][1], ah[mi][2], ah[mi][3], bl2, bl3);
            }
        }
        // pass 3: lo*hi (reuse bh)
        #pragma unroll
        for (int mi = 0; mi < 4; ++mi) {
            uint32_t al0, al1, al2, al3;
            ldm4(al0, al1, al2, al3, adr[mi] + OFF_AL);
            #pragma unroll
            for (int ni = 0; ni < 4; ++ni)
                mma16816(acc[mi][ni], al0, al1, al2, al3,
                         bh[ni >> 1][(ni & 1) * 2], bh[ni >> 1][(ni & 1) * 2 + 1]);
        }
    }
}

// ---------------------------------------------------------------------------
// Stage A: U[b][j][d] = sum_{w,c} k[b][j+w-1][c] * Wop[d][w*CH+c]
// ---------------------------------------------------------------------------
__device__ __forceinline__ void loadA_stage(uint32_t sbase, int b, int jt, int dt,
                                            int ch, int tid) {
    const int w  = ch >> 4;
    const int c0 = (ch & 15) * 32;
    #pragma unroll
    for (int u = 0; u < 2; ++u) {
        int f = tid + u * 256;             // 0..511
        int row = f >> 2, c16 = f & 3;
        uint32_t so = sw_off(row, c16 * 16);
        int jg = jt + row + w - 1;
        int ok = (jg >= 0 && jg < LK) ? 16 : 0;
        int jc = (jg >= 0 && jg < LK) ? jg : 0;
        size_t gi = ((size_t)b * LK + jc) * CH + c0 + c16 * 8;
        cpa16(sbase + so,          g_khi + gi, ok);
        cpa16(sbase + OFF_AL + so, g_klo + gi, ok);
        size_t wi = (size_t)(dt + row) * KTOT + w * CH + c0 + c16 * 8;
        cpa16(sbase + OFF_BH + so, g_Whi + wi, 16);
        cpa16(sbase + OFF_BL + so, g_Wlo + wi, 16);
    }
}

__global__ __launch_bounds__(256, 2) void gemmA_mma() {
    extern __shared__ __align__(16) uint8_t smem[];
    const int b  = blockIdx.z;
    const int jt = blockIdx.y * 128;
    const int dt = blockIdx.x * 128;
    const int tid = threadIdx.x, lane = tid & 31, wid = tid >> 5;
    const int wm = wid >> 2, wn = wid & 3;
    const int g = lane >> 2, t = lane & 3;
    const uint32_t sb = smem_u32(smem);
    const LdmCtx ctx = make_ctx(lane, wm, wn);

    float acc[4][4][4];
    #pragma unroll
    for (int a = 0; a < 4; ++a)
        #pragma unroll
        for (int bq = 0; bq < 4; ++bq)
            #pragma unroll
            for (int c = 0; c < 4; ++c) acc[a][bq][c] = 0.f;

    loadA_stage(sb,               b, jt, dt, 0, tid); CP_COMMIT();
    loadA_stage(sb + STAGE_BYTES, b, jt, dt, 1, tid); CP_COMMIT();
    for (int ch = 0; ch < 48; ++ch) {
        CP_WAIT1();
        __syncthreads();
        compute_chunk(sb + (uint32_t)(ch % NSTAGE) * STAGE_BYTES, ctx, acc);
        if (ch + 2 < 48)
            loadA_stage(sb + (uint32_t)((ch + 2) % NSTAGE) * STAGE_BYTES, b, jt, dt, ch + 2, tid);
        CP_COMMIT();
    }

    // epilogue: split fp32 -> bf16 hi/lo, store U (register packing only)
    #pragma unroll
    for (int mi = 0; mi < 4; ++mi) {
        #pragma unroll
        for (int ni = 0; ni < 4; ++ni) {
            int j0 = jt + wm * 64 + mi * 16 + g;
            int d0 = dt + wn * 32 + ni * 8 + 2 * t;
            #pragma unroll
            for (int rr = 0; rr < 2; ++rr) {
                float v0 = acc[mi][ni][rr * 2 + 0];
                float v1 = acc[mi][ni][rr * 2 + 1];
                float l0, l1;
                uint32_t hp = pack_hi(v0, v1, l0, l1);
                uint32_t lp = pack_bf(l0, l1);
                size_t o = ((size_t)b * LK + (j0 + rr * 8)) * DIM + d0;
                *reinterpret_cast<uint32_t*>(g_Uhi + o) = hp;
                *reinterpret_cast<uint32_t*>(g_Ulo + o) = lp;
            }
        }
    }
}

// ---------------------------------------------------------------------------
// Stage B: out[b][i][j] = q[b][i][:] . U[b][j][:] + qb[b,i] + bbj[b,j] + bias_b
// ---------------------------------------------------------------------------
__device__ __forceinline__ void loadB_stage(uint32_t sbase, int b, int it, int jt,
                                            int ch, int tid) {
    const int kt = ch * 32;
    #pragma unroll
    for (int u = 0; u < 2; ++u) {
        int f = tid + u * 256;
        int row = f >> 2, c16 = f & 3;
        uint32_t so = sw_off(row, c16 * 16);
        size_t qi = ((size_t)b * LQ + it + row) * DIM + kt + c16 * 8;
        cpa16(sbase + so,          g_qhi + qi, 16);
        cpa16(sbase + OFF_AL + so, g_qlo + qi, 16);
        size_t ui = ((size_t)b * LK + jt + row) * DIM + kt + c16 * 8;
        cpa16(sbase + OFF_BH + so, g_Uhi + ui, 16);
        cpa16(sbase + OFF_BL + so, g_Ulo + ui, 16);
    }
}

__global__ __launch_bounds__(256, 2) void gemmB_mma(const float* __restrict__ biasb,
                                                    float* __restrict__ out) {
    extern __shared__ __align__(16) uint8_t smem[];
    const int b  = blockIdx.z;
    const int it = blockIdx.y * 128;
    const int jt = blockIdx.x * 128;
    const int tid = threadIdx.x, lane = tid & 31, wid = tid >> 5;
    const int wm = wid >> 2, wn = wid & 3;
    const int g = lane >> 2, t = lane & 3;
    const uint32_t sb = smem_u32(smem);
    const LdmCtx ctx = make_ctx(lane, wm, wn);

    float acc[4][4][4];
    #pragma unroll
    for (int a = 0; a < 4; ++a)
        #pragma unroll
        for (int bq = 0; bq < 4; ++bq)
            #pragma unroll
            for (int c = 0; c < 4; ++c) acc[a][bq][c] = 0.f;

    loadB_stage(sb,               b, it, jt, 0, tid); CP_COMMIT();
    loadB_stage(sb + STAGE_BYTES, b, it, jt, 1, tid); CP_COMMIT();
    for (int ch = 0; ch < 16; ++ch) {
        CP_WAIT1();
        __syncthreads();
        compute_chunk(sb + (uint32_t)(ch % NSTAGE) * STAGE_BYTES, ctx, acc);
        if (ch + 2 < 16)
            loadB_stage(sb + (uint32_t)((ch + 2) % NSTAGE) * STAGE_BYTES, b, it, jt, ch + 2, tid);
        CP_COMMIT();
    }

    const float bB = biasb[0];
    #pragma unroll
    for (int mi = 0; mi < 4; ++mi) {
        int i0 = it + wm * 64 + mi * 16 + g;
        float cb0 = g_qb[b * LQ + i0] + bB;
        float cb1 = g_qb[b * LQ + i0 + 8] + bB;
        #pragma unroll
        for (int ni = 0; ni < 4; ++ni) {
            int j0 = jt + wn * 32 + ni * 8 + 2 * t;
            float bb0 = g_bbj[b * LK + j0];
            float bb1 = g_bbj[b * LK + j0 + 1];
            float2 r0 = make_float2(acc[mi][ni][0] + cb0 + bb0,
                                    acc[mi][ni][1] + cb0 + bb1);
            float2 r1 = make_float2(acc[mi][ni][2] + cb1 + bb0,
                                    acc[mi][ni][3] + cb1 + bb1);
            *reinterpret_cast<float2*>(out + ((size_t)b * LQ + i0) * LK + j0)     = r0;
            *reinterpret_cast<float2*>(out + ((size_t)b * LQ + i0 + 8) * LK + j0) = r1;
        }
    }
}

// ---------------------------------------------------------------------------
extern "C" void kernel_launch(void* const* d_in, const int* in_sizes, int n_in,
                              void* d_out, int out_size) {
    const float* q     = (const float*)d_in[0];   // (8,1024,512)
    const float* k     = (const float*)d_in[1];   // (8,1024,512)
    const float* W     = (const float*)d_in[2];   // (512,1536)
    const float* bk    = (const float*)d_in[3];   // (1536,)
    const float* Wb    = (const float*)d_in[4];   // (512,1)
    const float* bb    = (const float*)d_in[5];   // (1,)
    const float* biasb = (const float*)d_in[6];   // (1,)
    float* out = (float*)d_out;                   // (8,1024,1024)

    // idempotent, deterministic — no static guard
    cudaFuncSetAttribute(gemmA_mma, cudaFuncAttributeMaxDynamicSharedMemorySize, SMEM_TOTAL);
    cudaFuncSetAttribute(gemmB_mma, cudaFuncAttributeMaxDynamicSharedMemorySize, SMEM_TOTAL);

    // fused preamble: q/k each read exactly once
    fused_q_kernel<<<BATCH * LQ / 8, 256>>>(q, Wb, bb);     // 8 warps/block
    fused_k_kernel<<<BATCH * LK / 8, 256>>>(k, bk);
    wsplit_kernel<<<(DIM * KTOT + 255) / 256, 256>>>(W);
    combine_bbj_kernel<<<(BATCH * LK + 255) / 256, 256>>>();

    dim3 gA(DIM / 128, LK / 128, BATCH);          // (4, 8, 8)
    gemmA_mma<<<gA, 256, SMEM_TOTAL>>>();

    dim3 gB(LK / 128, LQ / 128, BATCH);           // (8, 8, 8)
    gemmB_mma<<<gB, 256, SMEM_TOTAL>>>(biasb, out);
}

// round 9
// speedup vs baseline: 4.0774x; 1.3229x over previous
#include <cuda_runtime.h>
#include <cuda_fp16.h>
#include <cstdint>

// Problem shapes (fixed by the dataset)
#define BATCH 8
#define LQ    1024
#define LK    1024
#define DIM   512
#define CH    512
#define KTOT  1536   // 3*CH

// ---------------------------------------------------------------------------
// Scratch (device globals). Referenced ONLY from device code (host-side
// &g_xxx yields the shadow symbol: the round-3/4 bug).
// fp16 2-product scheme: A-operands (k, q) stored hi-only; B-operands
// (W, U) stored hi+lo.
// ---------------------------------------------------------------------------
__device__ __half g_qh[BATCH * LQ * DIM];
__device__ __half g_kh[BATCH * LK * CH];
__device__ __half g_Wh[DIM * KTOT];              // Wop[d][w*CH+c] = W[d, c*3+w]
__device__ __half g_Wl[DIM * KTOT];
__device__ __half g_Uh[BATCH * LK * DIM];
__device__ __half g_Ul[BATCH * LK * DIM];
__device__ float g_qb[BATCH * LQ];
__device__ float g_t0[BATCH * LK];               // per-row dots for bbj conv
__device__ float g_t1[BATCH * LK];
__device__ float g_t2[BATCH * LK];

// ---------------------------------------------------------------------------
// PTX helpers
// ---------------------------------------------------------------------------
__device__ __forceinline__ void mma16816(float* c,
                                         uint32_t a0, uint32_t a1, uint32_t a2, uint32_t a3,
                                         uint32_t b0, uint32_t b1) {
    asm volatile(
        "mma.sync.aligned.m16n8k16.row.col.f32.f16.f16.f32 "
        "{%0,%1,%2,%3}, {%4,%5,%6,%7}, {%8,%9}, {%0,%1,%2,%3};"
        : "+f"(c[0]), "+f"(c[1]), "+f"(c[2]), "+f"(c[3])
        : "r"(a0), "r"(a1), "r"(a2), "r"(a3), "r"(b0), "r"(b1));
}

__device__ __forceinline__ void ldm4(uint32_t& r0, uint32_t& r1, uint32_t& r2, uint32_t& r3,
                                     uint32_t a) {
    asm volatile("ldmatrix.sync.aligned.m8n8.x4.shared.b16 {%0,%1,%2,%3}, [%4];"
                 : "=r"(r0), "=r"(r1), "=r"(r2), "=r"(r3) : "r"(a));
}

__device__ __forceinline__ uint32_t smem_u32(const void* p) {
    uint32_t a;
    asm("{ .reg .u64 t; cvta.to.shared.u64 t, %1; cvt.u32.u64 %0, t; }" : "=r"(a) : "l"(p));
    return a;
}

__device__ __forceinline__ void cpa16(uint32_t dst, const void* src, int srcsz) {
    asm volatile("cp.async.cg.shared.global [%0], [%1], 16, %2;"
                 :: "r"(dst), "l"(src), "r"(srcsz) : "memory");
}
#define CP_COMMIT() asm volatile("cp.async.commit_group;" ::: "memory")
#define CP_WAIT1()  asm volatile("cp.async.wait_group 1;" ::: "memory")

// smem tile: 128 rows x 64 bytes (32 fp16), XOR-swizzled:
//   phys = row*64 + (kb ^ (((row>>1)&3)<<4))
__device__ __forceinline__ uint32_t sw_off(int row, int kb) {
    return (uint32_t)(row * 64 + (kb ^ (((row >> 1) & 3) << 4)));
}

// fp16 hi/lo split packers (pure register ops)
__device__ __forceinline__ uint32_t pack_hi16(float a, float b, float& ra, float& rb) {
    __half ha = __float2half_rn(a);
    __half hb = __float2half_rn(b);
    ra = a - __half2float(ha);
    rb = b - __half2float(hb);
    return (uint32_t)__half_as_ushort(ha) | ((uint32_t)__half_as_ushort(hb) << 16);
}
__device__ __forceinline__ uint32_t pack_h16(float a, float b) {
    return (uint32_t)__half_as_ushort(__float2half_rn(a)) |
           ((uint32_t)__half_as_ushort(__float2half_rn(b)) << 16);
}

// ---------------------------------------------------------------------------
// Fused preamble (warp per row).
// fused_q: q -> fp16 hi AND qb[row] = q[row]·Wb + bb   (q read once)
// ---------------------------------------------------------------------------
__global__ void fused_q_kernel(const float* __restrict__ q,
                               const float* __restrict__ Wb,
                               const float* __restrict__ bb) {
    int gw   = (blockIdx.x * blockDim.x + threadIdx.x) >> 5;   // 0..8191
    int lane = threadIdx.x & 31;
    if (gw >= BATCH * LQ) return;
    const float4* qr  = reinterpret_cast<const float4*>(q) + (size_t)gw * 128;
    const float4* wb4 = reinterpret_cast<const float4*>(Wb);
    float s = 0.f;
    #pragma unroll
    for (int v = 0; v < 4; ++v) {
        int idx = lane + 32 * v;
        float4 x = qr[idx];
        float4 wv = wb4[idx];
        s += x.x * wv.x + x.y * wv.y + x.z * wv.z + x.w * wv.w;
        size_t o = (size_t)gw * 128 + idx;
        reinterpret_cast<uint2*>(g_qh)[o] =
            make_uint2(pack_h16(x.x, x.y), pack_h16(x.z, x.w));
    }
    #pragma unroll
    for (int o = 16; o; o >>= 1) s += __shfl_down_sync(0xFFFFFFFFu, s, o);
    if (lane == 0) g_qb[gw] = s + bb[0];
}

// fused_k: k -> fp16 hi AND t_w[row] = bk_w · k[row] for w=0,1,2
// (bbj assembled inline in gemmB epilogue: bbj[j]=t0[j-1]+t1[j]+t2[j+1])
__global__ void fused_k_kernel(const float* __restrict__ k,
                               const float* __restrict__ bk) {
    int gw   = (blockIdx.x * blockDim.x + threadIdx.x) >> 5;
    int lane = threadIdx.x & 31;
    if (gw >= BATCH * LK) return;
    const float4* kr  = reinterpret_cast<const float4*>(k) + (size_t)gw * 128;
    const float4* bk4 = reinterpret_cast<const float4*>(bk);
    float t0 = 0.f, t1 = 0.f, t2 = 0.f;
    #pragma unroll
    for (int v = 0; v < 4; ++v) {
        int idx = lane + 32 * v;          // float4 slot; c0 = 4*idx
        float4 x = kr[idx];
        float4 f0 = bk4[3 * idx + 0];
        float4 f1 = bk4[3 * idx + 1];
        float4 f2 = bk4[3 * idx + 2];
        t0 += x.x * f0.x + x.y * f0.w + x.z * f1.z + x.w * f2.y;
        t1 += x.x * f0.y + x.y * f1.x + x.z * f1.w + x.w * f2.z;
        t2 += x.x * f0.z + x.y * f1.y + x.z * f2.x + x.w * f2.w;
        size_t o = (size_t)gw * 128 + idx;
        reinterpret_cast<uint2*>(g_kh)[o] =
            make_uint2(pack_h16(x.x, x.y), pack_h16(x.z, x.w));
    }
    #pragma unroll
    for (int o = 16; o; o >>= 1) {
        t0 += __shfl_down_sync(0xFFFFFFFFu, t0, o);
        t1 += __shfl_down_sync(0xFFFFFFFFu, t1, o);
        t2 += __shfl_down_sync(0xFFFFFFFFu, t2, o);
    }
    if (lane == 0) { g_t0[gw] = t0; g_t1[gw] = t1; g_t2[gw] = t2; }
}

// W repack + fp16 hi/lo split: Wop[d][w*CH+c] = W[d, c*3+w]
__global__ void wsplit_kernel(const float* __restrict__ W) {
    int idx = blockIdx.x * blockDim.x + threadIdx.x;
    if (idx >= DIM * KTOT) return;
    int d  = idx / KTOT;
    int wc = idx % KTOT;
    int w  = wc / CH;
    int c  = wc % CH;
    float f = W[d * KTOT + c * 3 + w];
    __half h = __float2half_rn(f);
    g_Wh[idx] = h;
    g_Wl[idx] = __float2half_rn(f - __half2float(h));
}

// ---------------------------------------------------------------------------
// GEMM core: CTA 128x128, BK=32, 8 warps, warp tile 64x32.
// 3-stage cp.async ring; ldmatrix.x4; fp16 2-product:
//   acc += Ah*Bh + Ah*Bl    (fp32 accumulators)
// Stage: A@0 (8KB), Bh@8K, Bl@16K  -> 24KB/stage, 3 stages = 72KB.
// __launch_bounds__(256,2): 2 CTAs/SM.
// ---------------------------------------------------------------------------
#define OFF_BH 8192
#define OFF_BL 16384
#define STAGE_BYTES 24576
#define NSTAGE 3
#define SMEM_TOTAL  (NSTAGE * STAGE_BYTES)

struct LdmCtx {
    int tA[4], xA[4];   // per-mi: rowA*64, xor term
    int tB[2], xB[2];   // per-nii (pair of ni)
    int kkA, kkB;       // per-lane k-half byte offsets
};

__device__ __forceinline__ LdmCtx make_ctx(int lane, int wm, int wn) {
    LdmCtx c;
    #pragma unroll
    for (int mi = 0; mi < 4; ++mi) {
        int r = wm * 64 + mi * 16 + ((lane >> 3) & 1) * 8 + (lane & 7);
        c.tA[mi] = r * 64;
        c.xA[mi] = ((r >> 1) & 3) << 4;
    }
    #pragma unroll
    for (int nii = 0; nii < 2; ++nii) {
        int r = wn * 32 + nii * 16 + ((lane >> 4) & 1) * 8 + (lane & 7);
        c.tB[nii] = r * 64;
        c.xB[nii] = ((r >> 1) & 3) << 4;
    }
    c.kkA = (lane >> 4) * 16;          // A: matrices 2,3 take k+8 half
    c.kkB = ((lane >> 3) & 1) * 16;    // B: matrices 1,3 take k+8 half
    return c;
}

__device__ __forceinline__ void compute_chunk(uint32_t st, const LdmCtx& c,
                                              float acc[4][4][4]) {
    #pragma unroll
    for (int ks = 0; ks < 2; ++ks) {
        const int kbA = ks * 32 + c.kkA;
        const int kbB = ks * 32 + c.kkB;
        uint32_t ah[4][4], bh[2][4];
        #pragma unroll
        for (int mi = 0; mi < 4; ++mi)
            ldm4(ah[mi][0], ah[mi][1], ah[mi][2], ah[mi][3],
                 st + c.tA[mi] + (uint32_t)(kbA ^ c.xA[mi]));
        uint32_t bdr[2];
        #pragma unroll
        for (int nii = 0; nii < 2; ++nii) {
            bdr[nii] = st + OFF_BH + c.tB[nii] + (uint32_t)(kbB ^ c.xB[nii]);
            ldm4(bh[nii][0], bh[nii][1], bh[nii][2], bh[nii][3], bdr[nii]);
        }
        // pass 1: Ah * Bh
        #pragma unroll
        for (int mi = 0; mi < 4; ++mi)
            #pragma unroll
            for (int ni = 0; ni < 4; ++ni)
                mma16816(acc[mi][ni], ah[mi][0], ah[mi][1], ah[mi][2], ah[mi][3],
                         bh[ni >> 1][(ni & 1) * 2], bh[ni >> 1][(ni & 1) * 2 + 1]);
        // pass 2: Ah * Bl (reuse ah)
        #pragma unroll
        for (int nii = 0; nii < 2; ++nii) {
            uint32_t bl0, bl1, bl2, bl3;
            ldm4(bl0, bl1, bl2, bl3, bdr[nii] + (OFF_BL - OFF_BH));
            #pragma unroll
            for (int mi = 0; mi < 4; ++mi) {
                mma16816(acc[mi][nii * 2 + 0], ah[mi][0], ah[mi][1], ah[mi][2], ah[mi][3], bl0, bl1);
                mma16816(acc[mi][nii * 2 + 1], ah[mi][0], ah[mi][1], ah[mi][2], ah[mi][3], bl2, bl3);
            }
        }
    }
}

// ---------------------------------------------------------------------------
// Stage A: U[b][j][d] = sum_{w,c} k[b][j+w-1][c] * Wop[d][w*CH+c]
// ---------------------------------------------------------------------------
__device__ __forceinline__ void loadA_stage(uint32_t sbase, int b, int jt, int dt,
                                            int ch, int tid) {
    const int w  = ch >> 4;
    const int c0 = (ch & 15) * 32;
    #pragma unroll
    for (int u = 0; u < 2; ++u) {
        int f = tid + u * 256;             // 0..511
        int row = f >> 2, c16 = f & 3;
        uint32_t so = sw_off(row, c16 * 16);
        int jg = jt + row + w - 1;
        int ok = (jg >= 0 && jg < LK) ? 16 : 0;
        int jc = (jg >= 0 && jg < LK) ? jg : 0;
        size_t gi = ((size_t)b * LK + jc) * CH + c0 + c16 * 8;
        cpa16(sbase + so, g_kh + gi, ok);
        size_t wi = (size_t)(dt + row) * KTOT + w * CH + c0 + c16 * 8;
        cpa16(sbase + OFF_BH + so, g_Wh + wi, 16);
        cpa16(sbase + OFF_BL + so, g_Wl + wi, 16);
    }
}

__global__ __launch_bounds__(256, 2) void gemmA_mma() {
    extern __shared__ __align__(16) uint8_t smem[];
    const int b  = blockIdx.z;
    const int jt = blockIdx.y * 128;
    const int dt = blockIdx.x * 128;
    const int tid = threadIdx.x, lane = tid & 31, wid = tid >> 5;
    const int wm = wid >> 2, wn = wid & 3;
    const int g = lane >> 2, t = lane & 3;
    const uint32_t sb = smem_u32(smem);
    const LdmCtx ctx = make_ctx(lane, wm, wn);

    float acc[4][4][4];
    #pragma unroll
    for (int a = 0; a < 4; ++a)
        #pragma unroll
        for (int bq = 0; bq < 4; ++bq)
            #pragma unroll
            for (int c = 0; c < 4; ++c) acc[a][bq][c] = 0.f;

    loadA_stage(sb,               b, jt, dt, 0, tid); CP_COMMIT();
    loadA_stage(sb + STAGE_BYTES, b, jt, dt, 1, tid); CP_COMMIT();
    for (int ch = 0; ch < 48; ++ch) {
        CP_WAIT1();
        __syncthreads();
        compute_chunk(sb + (uint32_t)(ch % NSTAGE) * STAGE_BYTES, ctx, acc);
        if (ch + 2 < 48)
            loadA_stage(sb + (uint32_t)((ch + 2) % NSTAGE) * STAGE_BYTES, b, jt, dt, ch + 2, tid);
        CP_COMMIT();
    }

    // epilogue: split fp32 -> fp16 hi/lo, store U
    #pragma unroll
    for (int mi = 0; mi < 4; ++mi) {
        #pragma unroll
        for (int ni = 0; ni < 4; ++ni) {
            int j0 = jt + wm * 64 + mi * 16 + g;
            int d0 = dt + wn * 32 + ni * 8 + 2 * t;
            #pragma unroll
            for (int rr = 0; rr < 2; ++rr) {
                float v0 = acc[mi][ni][rr * 2 + 0];
                float v1 = acc[mi][ni][rr * 2 + 1];
                float l0, l1;
                uint32_t hp = pack_hi16(v0, v1, l0, l1);
                uint32_t lp = pack_h16(l0, l1);
                size_t o = ((size_t)b * LK + (j0 + rr * 8)) * DIM + d0;
                *reinterpret_cast<uint32_t*>(g_Uh + o) = hp;
                *reinterpret_cast<uint32_t*>(g_Ul + o) = lp;
            }
        }
    }
}

// ---------------------------------------------------------------------------
// Stage B: out[b][i][j] = q[b][i][:] . U[b][j][:] + qb[b,i] + bbj[b,j] + bias_b
// (bbj assembled inline from t0/t1/t2)
// ---------------------------------------------------------------------------
__device__ __forceinline__ void loadB_stage(uint32_t sbase, int b, int it, int jt,
                                            int ch, int tid) {
    const int kt = ch * 32;
    #pragma unroll
    for (int u = 0; u < 2; ++u) {
        int f = tid + u * 256;
        int row = f >> 2, c16 = f & 3;
        uint32_t so = sw_off(row, c16 * 16);
        size_t qi = ((size_t)b * LQ + it + row) * DIM + kt + c16 * 8;
        cpa16(sbase + so, g_qh + qi, 16);
        size_t ui = ((size_t)b * LK + jt + row) * DIM + kt + c16 * 8;
        cpa16(sbase + OFF_BH + so, g_Uh + ui, 16);
        cpa16(sbase + OFF_BL + so, g_Ul + ui, 16);
    }
}

__global__ __launch_bounds__(256, 2) void gemmB_mma(const float* __restrict__ biasb,
                                                    float* __restrict__ out) {
    extern __shared__ __align__(16) uint8_t smem[];
    const int b  = blockIdx.z;
    const int it = blockIdx.y * 128;
    const int jt = blockIdx.x * 128;
    const int tid = threadIdx.x, lane = tid & 31, wid = tid >> 5;
    const int wm = wid >> 2, wn = wid & 3;
    const int g = lane >> 2, t = lane & 3;
    const uint32_t sb = smem_u32(smem);
    const LdmCtx ctx = make_ctx(lane, wm, wn);

    float acc[4][4][4];
    #pragma unroll
    for (int a = 0; a < 4; ++a)
        #pragma unroll
        for (int bq = 0; bq < 4; ++bq)
            #pragma unroll
            for (int c = 0; c < 4; ++c) acc[a][bq][c] = 0.f;

    loadB_stage(sb,               b, it, jt, 0, tid); CP_COMMIT();
    loadB_stage(sb + STAGE_BYTES, b, it, jt, 1, tid); CP_COMMIT();
    for (int ch = 0; ch < 16; ++ch) {
        CP_WAIT1();
        __syncthreads();
        compute_chunk(sb + (uint32_t)(ch % NSTAGE) * STAGE_BYTES, ctx, acc);
        if (ch + 2 < 16)
            loadB_stage(sb + (uint32_t)((ch + 2) % NSTAGE) * STAGE_BYTES, b, it, jt, ch + 2, tid);
        CP_COMMIT();
    }

    // bbj inline: bbj[b,j] = t0[b,j-1] + t1[b,j] + t2[b,j+1] (edges clipped)
    float bbv[4][2];
    #pragma unroll
    for (int ni = 0; ni < 4; ++ni) {
        #pragma unroll
        for (int jj = 0; jj < 2; ++jj) {
            int j = jt + wn * 32 + ni * 8 + 2 * t + jj;   // 0..1023
            int idx = b * LK + j;
            float s = g_t1[idx];
            if (j > 0)      s += g_t0[idx - 1];
            if (j < LK - 1) s += g_t2[idx + 1];
            bbv[ni][jj] = s;
        }
    }

    const float bB = biasb[0];
    #pragma unroll
    for (int mi = 0; mi < 4; ++mi) {
        int i0 = it + wm * 64 + mi * 16 + g;
        float cb0 = g_qb[b * LQ + i0] + bB;
        float cb1 = g_qb[b * LQ + i0 + 8] + bB;
        #pragma unroll
        for (int ni = 0; ni < 4; ++ni) {
            int j0 = jt + wn * 32 + ni * 8 + 2 * t;
            float2 r0 = make_float2(acc[mi][ni][0] + cb0 + bbv[ni][0],
                                    acc[mi][ni][1] + cb0 + bbv[ni][1]);
            float2 r1 = make_float2(acc[mi][ni][2] + cb1 + bbv[ni][0],
                                    acc[mi][ni][3] + cb1 + bbv[ni][1]);
            *reinterpret_cast<float2*>(out + ((size_t)b * LQ + i0) * LK + j0)     = r0;
            *reinterpret_cast<float2*>(out + ((size_t)b * LQ + i0 + 8) * LK + j0) = r1;
        }
    }
}

// ---------------------------------------------------------------------------
extern "C" void kernel_launch(void* const* d_in, const int* in_sizes, int n_in,
                              void* d_out, int out_size) {
    const float* q     = (const float*)d_in[0];   // (8,1024,512)
    const float* k     = (const float*)d_in[1];   // (8,1024,512)
    const float* W     = (const float*)d_in[2];   // (512,1536)
    const float* bk    = (const float*)d_in[3];   // (1536,)
    const float* Wb    = (const float*)d_in[4];   // (512,1)
    const float* bb    = (const float*)d_in[5];   // (1,)
    const float* biasb = (const float*)d_in[6];   // (1,)
    float* out = (float*)d_out;                   // (8,1024,1024)

    // idempotent, deterministic — no static guard
    cudaFuncSetAttribute(gemmA_mma, cudaFuncAttributeMaxDynamicSharedMemorySize, SMEM_TOTAL);
    cudaFuncSetAttribute(gemmB_mma, cudaFuncAttributeMaxDynamicSharedMemorySize, SMEM_TOTAL);

    // fused preamble: q/k each read exactly once
    fused_q_kernel<<<BATCH * LQ / 8, 256>>>(q, Wb, bb);     // 8 warps/block
    fused_k_kernel<<<BATCH * LK / 8, 256>>>(k, bk);
    wsplit_kernel<<<(DIM * KTOT + 255) / 256, 256>>>(W);

    dim3 gA(DIM / 128, LK / 128, BATCH);          // (4, 8, 8)
    gemmA_mma<<<gA, 256, SMEM_TOTAL>>>();

    dim3 gB(LK / 128, LQ / 128, BATCH);           // (8, 8, 8)
    gemmB_mma<<<gB, 256, SMEM_TOTAL>>>(biasb, out);
}

// round 10
// speedup vs baseline: 6.0472x; 1.4831x over previous
#include <cuda_runtime.h>
#include <cuda_fp16.h>
#include <cstdint>

// Problem shapes (fixed by the dataset)
#define BATCH 8
#define LQ    1024
#define LK    1024
#define DIM   512
#define CH    512
#define KTOT  1536   // 3*CH

// ---------------------------------------------------------------------------
// Scratch (device globals). Referenced ONLY from device code (host-side
// &g_xxx yields the shadow symbol: the round-3/4 bug).
// Pure-fp16 scheme: all GEMM operands truncated to fp16 hi (error budget
// calibrated at ~2.1e-4 per truncation source, 4 sources -> ~4.2e-4).
// ---------------------------------------------------------------------------
__device__ __half g_qh[BATCH * LQ * DIM];
__device__ __half g_kh[BATCH * LK * CH];
__device__ __half g_Wh[DIM * KTOT];              // Wop[d][w*CH+c] = W[d, c*3+w]
__device__ __half g_Uh[BATCH * LK * DIM];
__device__ float g_qb[BATCH * LQ];
__device__ float g_t0[BATCH * LK];               // per-row dots for bbj conv
__device__ float g_t1[BATCH * LK];
__device__ float g_t2[BATCH * LK];

// ---------------------------------------------------------------------------
// PTX helpers
// ---------------------------------------------------------------------------
__device__ __forceinline__ void mma16816(float* c,
                                         uint32_t a0, uint32_t a1, uint32_t a2, uint32_t a3,
                                         uint32_t b0, uint32_t b1) {
    asm volatile(
        "mma.sync.aligned.m16n8k16.row.col.f32.f16.f16.f32 "
        "{%0,%1,%2,%3}, {%4,%5,%6,%7}, {%8,%9}, {%0,%1,%2,%3};"
        : "+f"(c[0]), "+f"(c[1]), "+f"(c[2]), "+f"(c[3])
        : "r"(a0), "r"(a1), "r"(a2), "r"(a3), "r"(b0), "r"(b1));
}

__device__ __forceinline__ void ldm4(uint32_t& r0, uint32_t& r1, uint32_t& r2, uint32_t& r3,
                                     uint32_t a) {
    asm volatile("ldmatrix.sync.aligned.m8n8.x4.shared.b16 {%0,%1,%2,%3}, [%4];"
                 : "=r"(r0), "=r"(r1), "=r"(r2), "=r"(r3) : "r"(a));
}

__device__ __forceinline__ uint32_t smem_u32(const void* p) {
    uint32_t a;
    asm("{ .reg .u64 t; cvta.to.shared.u64 t, %1; cvt.u32.u64 %0, t; }" : "=r"(a) : "l"(p));
    return a;
}

__device__ __forceinline__ void cpa16(uint32_t dst, const void* src, int srcsz) {
    asm volatile("cp.async.cg.shared.global [%0], [%1], 16, %2;"
                 :: "r"(dst), "l"(src), "r"(srcsz) : "memory");
}
#define CP_COMMIT() asm volatile("cp.async.commit_group;" ::: "memory")
#define CP_WAIT1()  asm volatile("cp.async.wait_group 1;" ::: "memory")

// smem tile: 128 rows x 64 bytes (32 fp16), XOR-swizzled:
//   phys = row*64 + (kb ^ (((row>>1)&3)<<4))
__device__ __forceinline__ uint32_t sw_off(int row, int kb) {
    return (uint32_t)(row * 64 + (kb ^ (((row >> 1) & 3) << 4)));
}

__device__ __forceinline__ uint32_t pack_h16(float a, float b) {
    return (uint32_t)__half_as_ushort(__float2half_rn(a)) |
           ((uint32_t)__half_as_ushort(__float2half_rn(b)) << 16);
}

// ---------------------------------------------------------------------------
// Fused preamble (warp per row).
// fused_q: q -> fp16 AND qb[row] = q[row]·Wb + bb   (q read once)
// ---------------------------------------------------------------------------
__global__ void fused_q_kernel(const float* __restrict__ q,
                               const float* __restrict__ Wb,
                               const float* __restrict__ bb) {
    int gw   = (blockIdx.x * blockDim.x + threadIdx.x) >> 5;   // 0..8191
    int lane = threadIdx.x & 31;
    if (gw >= BATCH * LQ) return;
    const float4* qr  = reinterpret_cast<const float4*>(q) + (size_t)gw * 128;
    const float4* wb4 = reinterpret_cast<const float4*>(Wb);
    float s = 0.f;
    #pragma unroll
    for (int v = 0; v < 4; ++v) {
        int idx = lane + 32 * v;
        float4 x = qr[idx];
        float4 wv = wb4[idx];
        s += x.x * wv.x + x.y * wv.y + x.z * wv.z + x.w * wv.w;
        size_t o = (size_t)gw * 128 + idx;
        reinterpret_cast<uint2*>(g_qh)[o] =
            make_uint2(pack_h16(x.x, x.y), pack_h16(x.z, x.w));
    }
    #pragma unroll
    for (int o = 16; o; o >>= 1) s += __shfl_down_sync(0xFFFFFFFFu, s, o);
    if (lane == 0) g_qb[gw] = s + bb[0];
}

// fused_k: k -> fp16 AND t_w[row] = bk_w · k[row] for w=0,1,2
// (bbj assembled inline in gemmB epilogue: bbj[j]=t0[j-1]+t1[j]+t2[j+1])
__global__ void fused_k_kernel(const float* __restrict__ k,
                               const float* __restrict__ bk) {
    int gw   = (blockIdx.x * blockDim.x + threadIdx.x) >> 5;
    int lane = threadIdx.x & 31;
    if (gw >= BATCH * LK) return;
    const float4* kr  = reinterpret_cast<const float4*>(k) + (size_t)gw * 128;
    const float4* bk4 = reinterpret_cast<const float4*>(bk);
    float t0 = 0.f, t1 = 0.f, t2 = 0.f;
    #pragma unroll
    for (int v = 0; v < 4; ++v) {
        int idx = lane + 32 * v;          // float4 slot; c0 = 4*idx
        float4 x = kr[idx];
        float4 f0 = bk4[3 * idx + 0];
        float4 f1 = bk4[3 * idx + 1];
        float4 f2 = bk4[3 * idx + 2];
        t0 += x.x * f0.x + x.y * f0.w + x.z * f1.z + x.w * f2.y;
        t1 += x.x * f0.y + x.y * f1.x + x.z * f1.w + x.w * f2.z;
        t2 += x.x * f0.z + x.y * f1.y + x.z * f2.x + x.w * f2.w;
        size_t o = (size_t)gw * 128 + idx;
        reinterpret_cast<uint2*>(g_kh)[o] =
            make_uint2(pack_h16(x.x, x.y), pack_h16(x.z, x.w));
    }
    #pragma unroll
    for (int o = 16; o; o >>= 1) {
        t0 += __shfl_down_sync(0xFFFFFFFFu, t0, o);
        t1 += __shfl_down_sync(0xFFFFFFFFu, t1, o);
        t2 += __shfl_down_sync(0xFFFFFFFFu, t2, o);
    }
    if (lane == 0) { g_t0[gw] = t0; g_t1[gw] = t1; g_t2[gw] = t2; }
}

// W repack + fp16: Wop[d][w*CH+c] = W[d, c*3+w]
__global__ void wsplit_kernel(const float* __restrict__ W) {
    int idx = blockIdx.x * blockDim.x + threadIdx.x;
    if (idx >= DIM * KTOT) return;
    int d  = idx / KTOT;
    int wc = idx % KTOT;
    int w  = wc / CH;
    int c  = wc % CH;
    g_Wh[idx] = __float2half_rn(W[d * KTOT + c * 3 + w]);
}

// ---------------------------------------------------------------------------
// GEMM core: CTA 128x128, 8 warps, warp tile 64x32, pure fp16 single product.
// Superchunk = 2 x BK=32 chunks computed per __syncthreads.
// Stage = [A0 8K][B0 8K][A1 8K][B1 8K] = 32KB; 3-stage ring = 96KB.
// Loads issued right after the sync (target buffer freed 2 iters ago),
// overlapping the whole compute phase.
// ---------------------------------------------------------------------------
#define OFF_B       8192
#define CHUNK_BYTES 16384
#define STAGE_BYTES 32768
#define NSTAGE 3
#define SMEM_TOTAL  (NSTAGE * STAGE_BYTES)

struct LdmCtx {
    int tA[4], xA[4];   // per-mi: rowA*64, xor term
    int tB[2], xB[2];   // per-nii (pair of ni)
    int kkA, kkB;       // per-lane k-half byte offsets
};

__device__ __forceinline__ LdmCtx make_ctx(int lane, int wm, int wn) {
    LdmCtx c;
    #pragma unroll
    for (int mi = 0; mi < 4; ++mi) {
        int r = wm * 64 + mi * 16 + ((lane >> 3) & 1) * 8 + (lane & 7);
        c.tA[mi] = r * 64;
        c.xA[mi] = ((r >> 1) & 3) << 4;
    }
    #pragma unroll
    for (int nii = 0; nii < 2; ++nii) {
        int r = wn * 32 + nii * 16 + ((lane >> 4) & 1) * 8 + (lane & 7);
        c.tB[nii] = r * 64;
        c.xB[nii] = ((r >> 1) & 3) << 4;
    }
    c.kkA = (lane >> 4) * 16;          // A: matrices 2,3 take k+8 half
    c.kkB = ((lane >> 3) & 1) * 16;    // B: matrices 1,3 take k+8 half
    return c;
}

__device__ __forceinline__ void compute_chunk(uint32_t st, const LdmCtx& c,
                                              float acc[4][4][4]) {
    #pragma unroll
    for (int ks = 0; ks < 2; ++ks) {
        const int kbA = ks * 32 + c.kkA;
        const int kbB = ks * 32 + c.kkB;
        uint32_t ah[4][4], bh[2][4];
        #pragma unroll
        for (int mi = 0; mi < 4; ++mi)
            ldm4(ah[mi][0], ah[mi][1], ah[mi][2], ah[mi][3],
                 st + c.tA[mi] + (uint32_t)(kbA ^ c.xA[mi]));
        #pragma unroll
        for (int nii = 0; nii < 2; ++nii)
            ldm4(bh[nii][0], bh[nii][1], bh[nii][2], bh[nii][3],
                 st + OFF_B + c.tB[nii] + (uint32_t)(kbB ^ c.xB[nii]));
        #pragma unroll
        for (int mi = 0; mi < 4; ++mi)
            #pragma unroll
            for (int ni = 0; ni < 4; ++ni)
                mma16816(acc[mi][ni], ah[mi][0], ah[mi][1], ah[mi][2], ah[mi][3],
                         bh[ni >> 1][(ni & 1) * 2], bh[ni >> 1][(ni & 1) * 2 + 1]);
    }
}

__device__ __forceinline__ void compute_super(uint32_t st, const LdmCtx& c,
                                              float acc[4][4][4]) {
    compute_chunk(st, c, acc);
    compute_chunk(st + CHUNK_BYTES, c, acc);
}

// ---------------------------------------------------------------------------
// Stage A: U[b][j][d] = sum_{w,c} k[b][j+w-1][c] * Wop[d][w*CH+c]
// K = 1536 as 48 BK=32 chunks = 24 superchunks.
// ---------------------------------------------------------------------------
__device__ __forceinline__ void loadA_chunk(uint32_t sbase, int b, int jt, int dt,
                                            int ch, int tid) {
    const int w  = ch >> 4;
    const int c0 = (ch & 15) * 32;
    #pragma unroll
    for (int u = 0; u < 2; ++u) {
        int f = tid + u * 256;             // 0..511
        int row = f >> 2, c16 = f & 3;
        uint32_t so = sw_off(row, c16 * 16);
        int jg = jt + row + w - 1;
        int ok = (jg >= 0 && jg < LK) ? 16 : 0;
        int jc = (jg >= 0 && jg < LK) ? jg : 0;
        size_t gi = ((size_t)b * LK + jc) * CH + c0 + c16 * 8;
        cpa16(sbase + so, g_kh + gi, ok);
        size_t wi = (size_t)(dt + row) * KTOT + w * CH + c0 + c16 * 8;
        cpa16(sbase + OFF_B + so, g_Wh + wi, 16);
    }
}

__device__ __forceinline__ void loadA_super(uint32_t sbase, int b, int jt, int dt,
                                            int sc, int tid) {
    loadA_chunk(sbase,               b, jt, dt, 2 * sc,     tid);
    loadA_chunk(sbase + CHUNK_BYTES, b, jt, dt, 2 * sc + 1, tid);
}

__global__ __launch_bounds__(256, 2) void gemmA_mma() {
    extern __shared__ __align__(16) uint8_t smem[];
    const int b  = blockIdx.z;
    const int jt = blockIdx.y * 128;
    const int dt = blockIdx.x * 128;
    const int tid = threadIdx.x, lane = tid & 31, wid = tid >> 5;
    const int wm = wid >> 2, wn = wid & 3;
    const int g = lane >> 2, t = lane & 3;
    const uint32_t sb = smem_u32(smem);
    const LdmCtx ctx = make_ctx(lane, wm, wn);

    float acc[4][4][4];
    #pragma unroll
    for (int a = 0; a < 4; ++a)
        #pragma unroll
        for (int bq = 0; bq < 4; ++bq)
            #pragma unroll
            for (int c = 0; c < 4; ++c) acc[a][bq][c] = 0.f;

    loadA_super(sb,               b, jt, dt, 0, tid); CP_COMMIT();
    loadA_super(sb + STAGE_BYTES, b, jt, dt, 1, tid); CP_COMMIT();
    for (int sc = 0; sc < 24; ++sc) {
        CP_WAIT1();
        __syncthreads();
        if (sc + 2 < 24)
            loadA_super(sb + (uint32_t)((sc + 2) % NSTAGE) * STAGE_BYTES, b, jt, dt, sc + 2, tid);
        CP_COMMIT();
        compute_super(sb + (uint32_t)(sc % NSTAGE) * STAGE_BYTES, ctx, acc);
    }

    // epilogue: store U as fp16
    #pragma unroll
    for (int mi = 0; mi < 4; ++mi) {
        #pragma unroll
        for (int ni = 0; ni < 4; ++ni) {
            int j0 = jt + wm * 64 + mi * 16 + g;
            int d0 = dt + wn * 32 + ni * 8 + 2 * t;
            #pragma unroll
            for (int rr = 0; rr < 2; ++rr) {
                uint32_t hp = pack_h16(acc[mi][ni][rr * 2 + 0], acc[mi][ni][rr * 2 + 1]);
                size_t o = ((size_t)b * LK + (j0 + rr * 8)) * DIM + d0;
                *reinterpret_cast<uint32_t*>(g_Uh + o) = hp;
            }
        }
    }
}

// ---------------------------------------------------------------------------
// Stage B: out[b][i][j] = q[b][i][:] . U[b][j][:] + qb[b,i] + bbj[b,j] + bias_b
// K = 512 as 16 chunks = 8 superchunks. bbj assembled inline from t0/t1/t2.
// ---------------------------------------------------------------------------
__device__ __forceinline__ void loadB_chunk(uint32_t sbase, int b, int it, int jt,
                                            int ch, int tid) {
    const int kt = ch * 32;
    #pragma unroll
    for (int u = 0; u < 2; ++u) {
        int f = tid + u * 256;
        int row = f >> 2, c16 = f & 3;
        uint32_t so = sw_off(row, c16 * 16);
        size_t qi = ((size_t)b * LQ + it + row) * DIM + kt + c16 * 8;
        cpa16(sbase + so, g_qh + qi, 16);
        size_t ui = ((size_t)b * LK + jt + row) * DIM + kt + c16 * 8;
        cpa16(sbase + OFF_B + so, g_Uh + ui, 16);
    }
}

__device__ __forceinline__ void loadB_super(uint32_t sbase, int b, int it, int jt,
                                            int sc, int tid) {
    loadB_chunk(sbase,               b, it, jt, 2 * sc,     tid);
    loadB_chunk(sbase + CHUNK_BYTES, b, it, jt, 2 * sc + 1, tid);
}

__global__ __launch_bounds__(256, 2) void gemmB_mma(const float* __restrict__ biasb,
                                                    float* __restrict__ out) {
    extern __shared__ __align__(16) uint8_t smem[];
    const int b  = blockIdx.z;
    const int it = blockIdx.y * 128;
    const int jt = blockIdx.x * 128;
    const int tid = threadIdx.x, lane = tid & 31, wid = tid >> 5;
    const int wm = wid >> 2, wn = wid & 3;
    const int g = lane >> 2, t = lane & 3;
    const uint32_t sb = smem_u32(smem);
    const LdmCtx ctx = make_ctx(lane, wm, wn);

    float acc[4][4][4];
    #pragma unroll
    for (int a = 0; a < 4; ++a)
        #pragma unroll
        for (int bq = 0; bq < 4; ++bq)
            #pragma unroll
            for (int c = 0; c < 4; ++c) acc[a][bq][c] = 0.f;

    loadB_super(sb,               b, it, jt, 0, tid); CP_COMMIT();
    loadB_super(sb + STAGE_BYTES, b, it, jt, 1, tid); CP_COMMIT();
    for (int sc = 0; sc < 8; ++sc) {
        CP_WAIT1();
        __syncthreads();
        if (sc + 2 < 8)
            loadB_super(sb + (uint32_t)((sc + 2) % NSTAGE) * STAGE_BYTES, b, it, jt, sc + 2, tid);
        CP_COMMIT();
        compute_super(sb + (uint32_t)(sc % NSTAGE) * STAGE_BYTES, ctx, acc);
    }

    // bbj inline: bbj[b,j] = t0[b,j-1] + t1[b,j] + t2[b,j+1] (edges clipped)
    float bbv[4][2];
    #pragma unroll
    for (int ni = 0; ni < 4; ++ni) {
        #pragma unroll
        for (int jj = 0; jj < 2; ++jj) {
            int j = jt + wn * 32 + ni * 8 + 2 * t + jj;   // 0..1023
            int idx = b * LK + j;
            float s = g_t1[idx];
            if (j > 0)      s += g_t0[idx - 1];
            if (j < LK - 1) s += g_t2[idx + 1];
            bbv[ni][jj] = s;
        }
    }

    const float bB = biasb[0];
    #pragma unroll
    for (int mi = 0; mi < 4; ++mi) {
        int i0 = it + wm * 64 + mi * 16 + g;
        float cb0 = g_qb[b * LQ + i0] + bB;
        float cb1 = g_qb[b * LQ + i0 + 8] + bB;
        #pragma unroll
        for (int ni = 0; ni < 4; ++ni) {
            int j0 = jt + wn * 32 + ni * 8 + 2 * t;
            float2 r0 = make_float2(acc[mi][ni][0] + cb0 + bbv[ni][0],
                                    acc[mi][ni][1] + cb0 + bbv[ni][1]);
            float2 r1 = make_float2(acc[mi][ni][2] + cb1 + bbv[ni][0],
                                    acc[mi][ni][3] + cb1 + bbv[ni][1]);
            *reinterpret_cast<float2*>(out + ((size_t)b * LQ + i0) * LK + j0)     = r0;
            *reinterpret_cast<float2*>(out + ((size_t)b * LQ + i0 + 8) * LK + j0) = r1;
        }
    }
}

// ---------------------------------------------------------------------------
extern "C" void kernel_launch(void* const* d_in, const int* in_sizes, int n_in,
                              void* d_out, int out_size) {
    const float* q     = (const float*)d_in[0];   // (8,1024,512)
    const float* k     = (const float*)d_in[1];   // (8,1024,512)
    const float* W     = (const float*)d_in[2];   // (512,1536)
    const float* bk    = (const float*)d_in[3];   // (1536,)
    const float* Wb    = (const float*)d_in[4];   // (512,1)
    const float* bb    = (const float*)d_in[5];   // (1,)
    const float* biasb = (const float*)d_in[6];   // (1,)
    float* out = (float*)d_out;                   // (8,1024,1024)

    // idempotent, deterministic — no static guard
    cudaFuncSetAttribute(gemmA_mma, cudaFuncAttributeMaxDynamicSharedMemorySize, SMEM_TOTAL);
    cudaFuncSetAttribute(gemmB_mma, cudaFuncAttributeMaxDynamicSharedMemorySize, SMEM_TOTAL);

    // fused preamble: q/k each read exactly once
    fused_q_kernel<<<BATCH * LQ / 8, 256>>>(q, Wb, bb);     // 8 warps/block
    fused_k_kernel<<<BATCH * LK / 8, 256>>>(k, bk);
    wsplit_kernel<<<(DIM * KTOT + 255) / 256, 256>>>(W);

    dim3 gA(DIM / 128, LK / 128, BATCH);          // (4, 8, 8)
    gemmA_mma<<<gA, 256, SMEM_TOTAL>>>();

    dim3 gB(LK / 128, LQ / 128, BATCH);           // (8, 8, 8)
    gemmB_mma<<<gB, 256, SMEM_TOTAL>>>(biasb, out);
}

// round 11
// speedup vs baseline: 6.1757x; 1.0213x over previous
#include <cuda_runtime.h>
#include <cuda_fp16.h>
#include <cstdint>

// Problem shapes (fixed by the dataset)
#define BATCH 8
#define LQ    1024
#define LK    1024
#define DIM   512
#define CH    512
#define KTOT  1536   // 3*CH

// ---------------------------------------------------------------------------
// Scratch (device globals). Referenced ONLY from device code (host-side
// &g_xxx yields the shadow symbol: the round-3/4 bug).
// ---------------------------------------------------------------------------
__device__ __half g_qh[BATCH * LQ * DIM];
__device__ __half g_kh[BATCH * LK * CH];
__device__ __half g_Wh[DIM * KTOT];              // Wop[d][w*CH+c] = W[d, c*3+w]
__device__ __half g_Uh[BATCH * LK * DIM];
__device__ float g_qb[BATCH * LQ];
__device__ float g_t0[BATCH * LK];               // per-row dots for bbj conv
__device__ float g_t1[BATCH * LK];
__device__ float g_t2[BATCH * LK];

// ---------------------------------------------------------------------------
// PTX helpers
// ---------------------------------------------------------------------------
__device__ __forceinline__ void mma16816(float* c,
                                         uint32_t a0, uint32_t a1, uint32_t a2, uint32_t a3,
                                         uint32_t b0, uint32_t b1) {
    asm volatile(
        "mma.sync.aligned.m16n8k16.row.col.f32.f16.f16.f32 "
        "{%0,%1,%2,%3}, {%4,%5,%6,%7}, {%8,%9}, {%0,%1,%2,%3};"
        : "+f"(c[0]), "+f"(c[1]), "+f"(c[2]), "+f"(c[3])
        : "r"(a0), "r"(a1), "r"(a2), "r"(a3), "r"(b0), "r"(b1));
}

__device__ __forceinline__ void ldm4(uint32_t& r0, uint32_t& r1, uint32_t& r2, uint32_t& r3,
                                     uint32_t a) {
    asm volatile("ldmatrix.sync.aligned.m8n8.x4.shared.b16 {%0,%1,%2,%3}, [%4];"
                 : "=r"(r0), "=r"(r1), "=r"(r2), "=r"(r3) : "r"(a));
}

__device__ __forceinline__ uint32_t smem_u32(const void* p) {
    uint32_t a;
    asm("{ .reg .u64 t; cvta.to.shared.u64 t, %1; cvt.u32.u64 %0, t; }" : "=r"(a) : "l"(p));
    return a;
}

__device__ __forceinline__ void cpa16(uint32_t dst, const void* src, int srcsz) {
    asm volatile("cp.async.cg.shared.global [%0], [%1], 16, %2;"
                 :: "r"(dst), "l"(src), "r"(srcsz) : "memory");
}
#define CP_COMMIT() asm volatile("cp.async.commit_group;" ::: "memory")
#define CP_WAIT1()  asm volatile("cp.async.wait_group 1;" ::: "memory")

// smem tile: 128 rows x 64 bytes (32 fp16), XOR-swizzled:
//   phys = row*64 + (kb ^ (((row>>1)&3)<<4))
__device__ __forceinline__ uint32_t sw_off(int row, int kb) {
    return (uint32_t)(row * 64 + (kb ^ (((row >> 1) & 3) << 4)));
}

__device__ __forceinline__ uint32_t pack_h16(float a, float b) {
    return (uint32_t)__half_as_ushort(__float2half_rn(a)) |
           ((uint32_t)__half_as_ushort(__float2half_rn(b)) << 16);
}

// ---------------------------------------------------------------------------
// Fused preamble: single launch, block-range dispatch.
//   blocks [0,1024):    q -> fp16 + qb row dots   (warp per row)
//   blocks [1024,2048):  k -> fp16 + t0/t1/t2 row dots
//   blocks [2048,5120):  W repack -> fp16
// ---------------------------------------------------------------------------
__global__ void preamble_kernel(const float* __restrict__ q,
                                const float* __restrict__ k,
                                const float* __restrict__ W,
                                const float* __restrict__ bk,
                                const float* __restrict__ Wb,
                                const float* __restrict__ bb) {
    int bid = blockIdx.x;
    int tid = threadIdx.x;
    if (bid < 1024) {
        int gw   = (bid * 256 + tid) >> 5;          // 0..8191
        int lane = tid & 31;
        const float4* qr  = reinterpret_cast<const float4*>(q) + (size_t)gw * 128;
        const float4* wb4 = reinterpret_cast<const float4*>(Wb);
        float s = 0.f;
        #pragma unroll
        for (int v = 0; v < 4; ++v) {
            int idx = lane + 32 * v;
            float4 x = qr[idx];
            float4 wv = wb4[idx];
            s += x.x * wv.x + x.y * wv.y + x.z * wv.z + x.w * wv.w;
            size_t o = (size_t)gw * 128 + idx;
            reinterpret_cast<uint2*>(g_qh)[o] =
                make_uint2(pack_h16(x.x, x.y), pack_h16(x.z, x.w));
        }
        #pragma unroll
        for (int o = 16; o; o >>= 1) s += __shfl_down_sync(0xFFFFFFFFu, s, o);
        if (lane == 0) g_qb[gw] = s + bb[0];
    } else if (bid < 2048) {
        int gw   = ((bid - 1024) * 256 + tid) >> 5;
        int lane = tid & 31;
        const float4* kr  = reinterpret_cast<const float4*>(k) + (size_t)gw * 128;
        const float4* bk4 = reinterpret_cast<const float4*>(bk);
        float t0 = 0.f, t1 = 0.f, t2 = 0.f;
        #pragma unroll
        for (int v = 0; v < 4; ++v) {
            int idx = lane + 32 * v;              // float4 slot; c0 = 4*idx
            float4 x = kr[idx];
            float4 f0 = bk4[3 * idx + 0];
            float4 f1 = bk4[3 * idx + 1];
            float4 f2 = bk4[3 * idx + 2];
            t0 += x.x * f0.x + x.y * f0.w + x.z * f1.z + x.w * f2.y;
            t1 += x.x * f0.y + x.y * f1.x + x.z * f1.w + x.w * f2.z;
            t2 += x.x * f0.z + x.y * f1.y + x.z * f2.x + x.w * f2.w;
            size_t o = (size_t)gw * 128 + idx;
            reinterpret_cast<uint2*>(g_kh)[o] =
                make_uint2(pack_h16(x.x, x.y), pack_h16(x.z, x.w));
        }
        #pragma unroll
        for (int o = 16; o; o >>= 1) {
            t0 += __shfl_down_sync(0xFFFFFFFFu, t0, o);
            t1 += __shfl_down_sync(0xFFFFFFFFu, t1, o);
            t2 += __shfl_down_sync(0xFFFFFFFFu, t2, o);
        }
        if (lane == 0) { g_t0[gw] = t0; g_t1[gw] = t1; g_t2[gw] = t2; }
    } else {
        int idx = (bid - 2048) * 256 + tid;       // 0..786431
        int d  = idx / KTOT;
        int wc = idx % KTOT;
        int w  = wc / CH;
        int c  = wc % CH;
        g_Wh[idx] = __float2half_rn(W[d * KTOT + c * 3 + w]);
    }
}

// ---------------------------------------------------------------------------
// GEMM core: CTA 128x128, 4 warps (2x2), warp tile 64x64, 128 threads.
// Pure fp16 single product, fp32 accumulators (128 regs).
// Superchunk = 2 x BK=32 chunks per __syncthreads; 3-stage 96KB ring; occ 2.
// Crossbar bytes/MMA: 128 (vs 192 for 64x32 warps) -> ceiling tensor% ~67%.
// ---------------------------------------------------------------------------
#define OFF_B       8192
#define CHUNK_BYTES 16384
#define STAGE_BYTES 32768
#define NSTAGE 3
#define SMEM_TOTAL  (NSTAGE * STAGE_BYTES)

struct LdmCtx {
    int tA[4], xA[4];   // per-mi  (16 m-rows each)
    int tB[4], xB[4];   // per-nii (16 n-rows each)
    int kkA, kkB;       // per-lane k-half byte offsets
};

__device__ __forceinline__ LdmCtx make_ctx(int lane, int wm, int wn) {
    LdmCtx c;
    #pragma unroll
    for (int mi = 0; mi < 4; ++mi) {
        int r = wm * 64 + mi * 16 + ((lane >> 3) & 1) * 8 + (lane & 7);
        c.tA[mi] = r * 64;
        c.xA[mi] = ((r >> 1) & 3) << 4;
    }
    #pragma unroll
    for (int nii = 0; nii < 4; ++nii) {
        int r = wn * 64 + nii * 16 + ((lane >> 4) & 1) * 8 + (lane & 7);
        c.tB[nii] = r * 64;
        c.xB[nii] = ((r >> 1) & 3) << 4;
    }
    c.kkA = (lane >> 4) * 16;          // A: matrices 2,3 take k+8 half
    c.kkB = ((lane >> 3) & 1) * 16;    // B: matrices 1,3 take k+8 half
    return c;
}

__device__ __forceinline__ void compute_chunk(uint32_t st, const LdmCtx& c,
                                              float acc[4][8][4]) {
    #pragma unroll
    for (int ks = 0; ks < 2; ++ks) {
        const int kbA = ks * 32 + c.kkA;
        const int kbB = ks * 32 + c.kkB;
        uint32_t ah[4][4], bh[4][4];
        #pragma unroll
        for (int mi = 0; mi < 4; ++mi)
            ldm4(ah[mi][0], ah[mi][1], ah[mi][2], ah[mi][3],
                 st + c.tA[mi] + (uint32_t)(kbA ^ c.xA[mi]));
        #pragma unroll
        for (int nii = 0; nii < 4; ++nii)
            ldm4(bh[nii][0], bh[nii][1], bh[nii][2], bh[nii][3],
                 st + OFF_B + c.tB[nii] + (uint32_t)(kbB ^ c.xB[nii]));
        #pragma unroll
        for (int mi = 0; mi < 4; ++mi)
            #pragma unroll
            for (int ni = 0; ni < 8; ++ni)
                mma16816(acc[mi][ni], ah[mi][0], ah[mi][1], ah[mi][2], ah[mi][3],
                         bh[ni >> 1][(ni & 1) * 2], bh[ni >> 1][(ni & 1) * 2 + 1]);
    }
}

__device__ __forceinline__ void compute_super(uint32_t st, const LdmCtx& c,
                                              float acc[4][8][4]) {
    compute_chunk(st, c, acc);
    compute_chunk(st + CHUNK_BYTES, c, acc);
}

// ---------------------------------------------------------------------------
// Stage A: U[b][j][d] = sum_{w,c} k[b][j+w-1][c] * Wop[d][w*CH+c]
// K = 1536 as 48 BK=32 chunks = 24 superchunks.
// ---------------------------------------------------------------------------
__device__ __forceinline__ void loadA_chunk(uint32_t sbase, int b, int jt, int dt,
                                            int ch, int tid) {
    const int w  = ch >> 4;
    const int c0 = (ch & 15) * 32;
    #pragma unroll
    for (int u = 0; u < 4; ++u) {
        int f = tid + u * 128;             // 0..511
        int row = f >> 2, c16 = f & 3;
        uint32_t so = sw_off(row, c16 * 16);
        int jg = jt + row + w - 1;
        int ok = (jg >= 0 && jg < LK) ? 16 : 0;
        int jc = (jg >= 0 && jg < LK) ? jg : 0;
        size_t gi = ((size_t)b * LK + jc) * CH + c0 + c16 * 8;
        cpa16(sbase + so, g_kh + gi, ok);
        size_t wi = (size_t)(dt + row) * KTOT + w * CH + c0 + c16 * 8;
        cpa16(sbase + OFF_B + so, g_Wh + wi, 16);
    }
}

__device__ __forceinline__ void loadA_super(uint32_t sbase, int b, int jt, int dt,
                                            int sc, int tid) {
    loadA_chunk(sbase,               b, jt, dt, 2 * sc,     tid);
    loadA_chunk(sbase + CHUNK_BYTES, b, jt, dt, 2 * sc + 1, tid);
}

__global__ __launch_bounds__(128, 2) void gemmA_mma() {
    extern __shared__ __align__(16) uint8_t smem[];
    const int b  = blockIdx.z;
    const int jt = blockIdx.y * 128;
    const int dt = blockIdx.x * 128;
    const int tid = threadIdx.x, lane = tid & 31, wid = tid >> 5;
    const int wm = wid >> 1, wn = wid & 1;
    const int g = lane >> 2, t = lane & 3;
    const uint32_t sb = smem_u32(smem);
    const LdmCtx ctx = make_ctx(lane, wm, wn);

    float acc[4][8][4];
    #pragma unroll
    for (int a = 0; a < 4; ++a)
        #pragma unroll
        for (int bq = 0; bq < 8; ++bq)
            #pragma unroll
            for (int c = 0; c < 4; ++c) acc[a][bq][c] = 0.f;

    loadA_super(sb,               b, jt, dt, 0, tid); CP_COMMIT();
    loadA_super(sb + STAGE_BYTES, b, jt, dt, 1, tid); CP_COMMIT();
    for (int sc = 0; sc < 24; ++sc) {
        CP_WAIT1();
        __syncthreads();
        if (sc + 2 < 24)
            loadA_super(sb + (uint32_t)((sc + 2) % NSTAGE) * STAGE_BYTES, b, jt, dt, sc + 2, tid);
        CP_COMMIT();
        compute_super(sb + (uint32_t)(sc % NSTAGE) * STAGE_BYTES, ctx, acc);
    }

    // epilogue: store U as fp16
    #pragma unroll
    for (int mi = 0; mi < 4; ++mi) {
        #pragma unroll
        for (int ni = 0; ni < 8; ++ni) {
            int j0 = jt + wm * 64 + mi * 16 + g;
            int d0 = dt + wn * 64 + ni * 8 + 2 * t;
            #pragma unroll
            for (int rr = 0; rr < 2; ++rr) {
                uint32_t hp = pack_h16(acc[mi][ni][rr * 2 + 0], acc[mi][ni][rr * 2 + 1]);
                size_t o = ((size_t)b * LK + (j0 + rr * 8)) * DIM + d0;
                *reinterpret_cast<uint32_t*>(g_Uh + o) = hp;
            }
        }
    }
}

// ---------------------------------------------------------------------------
// Stage B: out[b][i][j] = q[b][i][:] . U[b][j][:] + qb[b,i] + bbj[b,j] + bias_b
// K = 512 as 16 chunks = 8 superchunks. bbj assembled inline from t0/t1/t2.
// ---------------------------------------------------------------------------
__device__ __forceinline__ void loadB_chunk(uint32_t sbase, int b, int it, int jt,
                                            int ch, int tid) {
    const int kt = ch * 32;
    #pragma unroll
    for (int u = 0; u < 4; ++u) {
        int f = tid + u * 128;
        int row = f >> 2, c16 = f & 3;
        uint32_t so = sw_off(row, c16 * 16);
        size_t qi = ((size_t)b * LQ + it + row) * DIM + kt + c16 * 8;
        cpa16(sbase + so, g_qh + qi, 16);
        size_t ui = ((size_t)b * LK + jt + row) * DIM + kt + c16 * 8;
        cpa16(sbase + OFF_B + so, g_Uh + ui, 16);
    }
}

__device__ __forceinline__ void loadB_super(uint32_t sbase, int b, int it, int jt,
                                            int sc, int tid) {
    loadB_chunk(sbase,               b, it, jt, 2 * sc,     tid);
    loadB_chunk(sbase + CHUNK_BYTES, b, it, jt, 2 * sc + 1, tid);
}

__global__ __launch_bounds__(128, 2) void gemmB_mma(const float* __restrict__ biasb,
                                                    float* __restrict__ out) {
    extern __shared__ __align__(16) uint8_t smem[];
    const int b  = blockIdx.z;
    const int it = blockIdx.y * 128;
    const int jt = blockIdx.x * 128;
    const int tid = threadIdx.x, lane = tid & 31, wid = tid >> 5;
    const int wm = wid >> 1, wn = wid & 1;
    const int g = lane >> 2, t = lane & 3;
    const uint32_t sb = smem_u32(smem);
    const LdmCtx ctx = make_ctx(lane, wm, wn);

    float acc[4][8][4];
    #pragma unroll
    for (int a = 0; a < 4; ++a)
        #pragma unroll
        for (int bq = 0; bq < 8; ++bq)
            #pragma unroll
            for (int c = 0; c < 4; ++c) acc[a][bq][c] = 0.f;

    loadB_super(sb,               b, it, jt, 0, tid); CP_COMMIT();
    loadB_super(sb + STAGE_BYTES, b, it, jt, 1, tid); CP_COMMIT();
    for (int sc = 0; sc < 8; ++sc) {
        CP_WAIT1();
        __syncthreads();
        if (sc + 2 < 8)
            loadB_super(sb + (uint32_t)((sc + 2) % NSTAGE) * STAGE_BYTES, b, it, jt, sc + 2, tid);
        CP_COMMIT();
        compute_super(sb + (uint32_t)(sc % NSTAGE) * STAGE_BYTES, ctx, acc);
    }

    // bbj inline: bbj[b,j] = t0[b,j-1] + t1[b,j] + t2[b,j+1] (edges clipped)
    float bbv[8][2];
    #pragma unroll
    for (int ni = 0; ni < 8; ++ni) {
        #pragma unroll
        for (int jj = 0; jj < 2; ++jj) {
            int j = jt + wn * 64 + ni * 8 + 2 * t + jj;   // 0..1023
            int idx = b * LK + j;
            float s = g_t1[idx];
            if (j > 0)      s += g_t0[idx - 1];
            if (j < LK - 1) s += g_t2[idx + 1];
            bbv[ni][jj] = s;
        }
    }

    const float bB = biasb[0];
    #pragma unroll
    for (int mi = 0; mi < 4; ++mi) {
        int i0 = it + wm * 64 + mi * 16 + g;
        float cb0 = g_qb[b * LQ + i0] + bB;
        float cb1 = g_qb[b * LQ + i0 + 8] + bB;
        #pragma unroll
        for (int ni = 0; ni < 8; ++ni) {
            int j0 = jt + wn * 64 + ni * 8 + 2 * t;
            float2 r0 = make_float2(acc[mi][ni][0] + cb0 + bbv[ni][0],
                                    acc[mi][ni][1] + cb0 + bbv[ni][1]);
            float2 r1 = make_float2(acc[mi][ni][2] + cb1 + bbv[ni][0],
                                    acc[mi][ni][3] + cb1 + bbv[ni][1]);
            *reinterpret_cast<float2*>(out + ((size_t)b * LQ + i0) * LK + j0)     = r0;
            *reinterpret_cast<float2*>(out + ((size_t)b * LQ + i0 + 8) * LK + j0) = r1;
        }
    }
}

// ---------------------------------------------------------------------------
extern "C" void kernel_launch(void* const* d_in, const int* in_sizes, int n_in,
                              void* d_out, int out_size) {
    const float* q     = (const float*)d_in[0];   // (8,1024,512)
    const float* k     = (const float*)d_in[1];   // (8,1024,512)
    const float* W     = (const float*)d_in[2];   // (512,1536)
    const float* bk    = (const float*)d_in[3];   // (1536,)
    const float* Wb    = (const float*)d_in[4];   // (512,1)
    const float* bb    = (const float*)d_in[5];   // (1,)
    const float* biasb = (const float*)d_in[6];   // (1,)
    float* out = (float*)d_out;                   // (8,1024,1024)

    // idempotent, deterministic — no static guard
    cudaFuncSetAttribute(gemmA_mma, cudaFuncAttributeMaxDynamicSharedMemorySize, SMEM_TOTAL);
    cudaFuncSetAttribute(gemmB_mma, cudaFuncAttributeMaxDynamicSharedMemorySize, SMEM_TOTAL);

    // fused single-launch preamble: q/k each read exactly once
    preamble_kernel<<<5120, 256>>>(q, k, W, bk, Wb, bb);

    dim3 gA(DIM / 128, LK / 128, BATCH);          // (4, 8, 8)
    gemmA_mma<<<gA, 128, SMEM_TOTAL>>>();

    dim3 gB(LK / 128, LQ / 128, BATCH);           // (8, 8, 8)
    gemmB_mma<<<gB, 128, SMEM_TOTAL>>>(biasb, out);
}

// round 12
// speedup vs baseline: 6.1778x; 1.0003x over previous
#include <cuda_runtime.h>
#include <cuda_fp16.h>
#include <cstdint>

// Problem shapes (fixed by the dataset)
#define BATCH 8
#define LQ    1024
#define LK    1024
#define DIM   512
#define CH    512
#define KTOT  1536   // 3*CH

// ---------------------------------------------------------------------------
// Scratch (device globals). Referenced ONLY from device code (host-side
// &g_xxx yields the shadow symbol: the round-3/4 bug).
// ---------------------------------------------------------------------------
__device__ __half g_qh[BATCH * LQ * DIM];
__device__ __half g_kh[BATCH * LK * CH];
__device__ __half g_Wh[DIM * KTOT];              // Wop[d][w*CH+c] = W[d, c*3+w]
__device__ __half g_Uh[BATCH * LK * DIM];
__device__ float g_qb[BATCH * LQ];
__device__ float g_t0[BATCH * LK];               // per-row dots for bbj conv
__device__ float g_t1[BATCH * LK];
__device__ float g_t2[BATCH * LK];

// ---------------------------------------------------------------------------
// PTX helpers
// ---------------------------------------------------------------------------
__device__ __forceinline__ void mma16816(float* c,
                                         uint32_t a0, uint32_t a1, uint32_t a2, uint32_t a3,
                                         uint32_t b0, uint32_t b1) {
    asm volatile(
        "mma.sync.aligned.m16n8k16.row.col.f32.f16.f16.f32 "
        "{%0,%1,%2,%3}, {%4,%5,%6,%7}, {%8,%9}, {%0,%1,%2,%3};"
        : "+f"(c[0]), "+f"(c[1]), "+f"(c[2]), "+f"(c[3])
        : "r"(a0), "r"(a1), "r"(a2), "r"(a3), "r"(b0), "r"(b1));
}

__device__ __forceinline__ void ldm4(uint32_t& r0, uint32_t& r1, uint32_t& r2, uint32_t& r3,
                                     uint32_t a) {
    asm volatile("ldmatrix.sync.aligned.m8n8.x4.shared.b16 {%0,%1,%2,%3}, [%4];"
                 : "=r"(r0), "=r"(r1), "=r"(r2), "=r"(r3) : "r"(a));
}

__device__ __forceinline__ uint32_t smem_u32(const void* p) {
    uint32_t a;
    asm("{ .reg .u64 t; cvta.to.shared.u64 t, %1; cvt.u32.u64 %0, t; }" : "=r"(a) : "l"(p));
    return a;
}

__device__ __forceinline__ void cpa16(uint32_t dst, const void* src, int srcsz) {
    asm volatile("cp.async.cg.shared.global [%0], [%1], 16, %2;"
                 :: "r"(dst), "l"(src), "r"(srcsz) : "memory");
}
#define CP_COMMIT() asm volatile("cp.async.commit_group;" ::: "memory")
#define CP_WAIT1()  asm volatile("cp.async.wait_group 1;" ::: "memory")

// smem tile: 128 rows x 64 bytes (32 fp16), XOR-swizzled:
//   phys = row*64 + (kb ^ (((row>>1)&3)<<4))
__device__ __forceinline__ uint32_t sw_off(int row, int kb) {
    return (uint32_t)(row * 64 + (kb ^ (((row >> 1) & 3) << 4)));
}

__device__ __forceinline__ uint32_t pack_h16(float a, float b) {
    return (uint32_t)__half_as_ushort(__float2half_rn(a)) |
           ((uint32_t)__half_as_ushort(__float2half_rn(b)) << 16);
}

// ---------------------------------------------------------------------------
// Fused preamble: single launch, block-range dispatch.
//   blocks [0,1024):     q -> fp16 + qb row dots   (warp per row)
//   blocks [1024,2048):  k -> fp16 + t0/t1/t2 row dots
//   blocks [2048,3072):  W repack -> fp16 (coalesced: thread per (d,c) triple)
// ---------------------------------------------------------------------------
__global__ void preamble_kernel(const float* __restrict__ q,
                                const float* __restrict__ k,
                                const float* __restrict__ W,
                                const float* __restrict__ bk,
                                const float* __restrict__ Wb,
                                const float* __restrict__ bb) {
    int bid = blockIdx.x;
    int tid = threadIdx.x;
    if (bid < 1024) {
        int gw   = (bid * 256 + tid) >> 5;          // 0..8191
        int lane = tid & 31;
        const float4* qr  = reinterpret_cast<const float4*>(q) + (size_t)gw * 128;
        const float4* wb4 = reinterpret_cast<const float4*>(Wb);
        float s = 0.f;
        #pragma unroll
        for (int v = 0; v < 4; ++v) {
            int idx = lane + 32 * v;
            float4 x = qr[idx];
            float4 wv = wb4[idx];
            s += x.x * wv.x + x.y * wv.y + x.z * wv.z + x.w * wv.w;
            size_t o = (size_t)gw * 128 + idx;
            reinterpret_cast<uint2*>(g_qh)[o] =
                make_uint2(pack_h16(x.x, x.y), pack_h16(x.z, x.w));
        }
        #pragma unroll
        for (int o = 16; o; o >>= 1) s += __shfl_down_sync(0xFFFFFFFFu, s, o);
        if (lane == 0) g_qb[gw] = s + bb[0];
    } else if (bid < 2048) {
        int gw   = ((bid - 1024) * 256 + tid) >> 5;
        int lane = tid & 31;
        const float4* kr  = reinterpret_cast<const float4*>(k) + (size_t)gw * 128;
        const float4* bk4 = reinterpret_cast<const float4*>(bk);
        float t0 = 0.f, t1 = 0.f, t2 = 0.f;
        #pragma unroll
        for (int v = 0; v < 4; ++v) {
            int idx = lane + 32 * v;              // float4 slot; c0 = 4*idx
            float4 x = kr[idx];
            float4 f0 = bk4[3 * idx + 0];
            float4 f1 = bk4[3 * idx + 1];
            float4 f2 = bk4[3 * idx + 2];
            t0 += x.x * f0.x + x.y * f0.w + x.z * f1.z + x.w * f2.y;
            t1 += x.x * f0.y + x.y * f1.x + x.z * f1.w + x.w * f2.z;
            t2 += x.x * f0.z + x.y * f1.y + x.z * f2.x + x.w * f2.w;
            size_t o = (size_t)gw * 128 + idx;
            reinterpret_cast<uint2*>(g_kh)[o] =
                make_uint2(pack_h16(x.x, x.y), pack_h16(x.z, x.w));
        }
        #pragma unroll
        for (int o = 16; o; o >>= 1) {
            t0 += __shfl_down_sync(0xFFFFFFFFu, t0, o);
            t1 += __shfl_down_sync(0xFFFFFFFFu, t1, o);
            t2 += __shfl_down_sync(0xFFFFFFFFu, t2, o);
        }
        if (lane == 0) { g_t0[gw] = t0; g_t1[gw] = t1; g_t2[gw] = t2; }
    } else {
        // W repack, coalesced: thread handles one (d,c) triple.
        int t3 = (bid - 2048) * 256 + tid;        // 0..262143
        int d  = t3 / CH;
        int cc = t3 % CH;
        const float* src = W + (size_t)d * KTOT + cc * 3;
        float w0 = src[0], w1 = src[1], w2 = src[2];
        size_t dst = (size_t)d * KTOT + cc;
        g_Wh[dst]          = __float2half_rn(w0);
        g_Wh[dst + CH]     = __float2half_rn(w1);
        g_Wh[dst + 2 * CH] = __float2half_rn(w2);
    }
}

// ---------------------------------------------------------------------------
// GEMM core: CTA 128x128, 4 warps (2x2), warp tile 64x64, 128 threads.
// Pure fp16 single product, fp32 accumulators (128 regs).
// Register double-buffered fragments: frags(ks+1) issued BEFORE MMAs(ks),
// so LDSM latency is covered by ~32 MMAs (volatile asm preserves this order).
// Superchunk = 2 x BK=32 chunks per __syncthreads; 3-stage 96KB ring; occ 2.
// ---------------------------------------------------------------------------
#define OFF_B       8192
#define CHUNK_BYTES 16384
#define STAGE_BYTES 32768
#define NSTAGE 3
#define SMEM_TOTAL  (NSTAGE * STAGE_BYTES)

struct LdmCtx {
    int tA[4], xA[4];   // per-mi  (16 m-rows each)
    int tB[4], xB[4];   // per-nii (16 n-rows each)
    int kkA, kkB;       // per-lane k-half byte offsets
};

__device__ __forceinline__ LdmCtx make_ctx(int lane, int wm, int wn) {
    LdmCtx c;
    #pragma unroll
    for (int mi = 0; mi < 4; ++mi) {
        int r = wm * 64 + mi * 16 + ((lane >> 3) & 1) * 8 + (lane & 7);
        c.tA[mi] = r * 64;
        c.xA[mi] = ((r >> 1) & 3) << 4;
    }
    #pragma unroll
    for (int nii = 0; nii < 4; ++nii) {
        int r = wn * 64 + nii * 16 + ((lane >> 4) & 1) * 8 + (lane & 7);
        c.tB[nii] = r * 64;
        c.xB[nii] = ((r >> 1) & 3) << 4;
    }
    c.kkA = (lane >> 4) * 16;          // A: matrices 2,3 take k+8 half
    c.kkB = ((lane >> 3) & 1) * 16;    // B: matrices 1,3 take k+8 half
    return c;
}

// Load all fragments for k-step ks (0..3) of a superchunk.
__device__ __forceinline__ void load_frags(uint32_t st, const LdmCtx& c, int ks,
                                           uint32_t ah[4][4], uint32_t bh[4][4]) {
    const uint32_t base = st + (uint32_t)(ks >> 1) * CHUNK_BYTES;
    const int kbA = (ks & 1) * 32 + c.kkA;
    const int kbB = (ks & 1) * 32 + c.kkB;
    #pragma unroll
    for (int mi = 0; mi < 4; ++mi)
        ldm4(ah[mi][0], ah[mi][1], ah[mi][2], ah[mi][3],
             base + c.tA[mi] + (uint32_t)(kbA ^ c.xA[mi]));
    #pragma unroll
    for (int nii = 0; nii < 4; ++nii)
        ldm4(bh[nii][0], bh[nii][1], bh[nii][2], bh[nii][3],
             base + OFF_B + c.tB[nii] + (uint32_t)(kbB ^ c.xB[nii]));
}

__device__ __forceinline__ void mma_block(float acc[4][8][4],
                                          uint32_t ah[4][4], uint32_t bh[4][4]) {
    #pragma unroll
    for (int mi = 0; mi < 4; ++mi)
        #pragma unroll
        for (int ni = 0; ni < 8; ++ni)
            mma16816(acc[mi][ni], ah[mi][0], ah[mi][1], ah[mi][2], ah[mi][3],
                     bh[ni >> 1][(ni & 1) * 2], bh[ni >> 1][(ni & 1) * 2 + 1]);
}

// Superchunk = 4 k-steps (2 chunks), register double-buffered.
__device__ __forceinline__ void compute_super(uint32_t st, const LdmCtx& c,
                                              float acc[4][8][4]) {
    uint32_t a0[4][4], b0[4][4], a1[4][4], b1[4][4];
    load_frags(st, c, 0, a0, b0);
    load_frags(st, c, 1, a1, b1);   // in flight over first MMA block
    mma_block(acc, a0, b0);
    load_frags(st, c, 2, a0, b0);
    mma_block(acc, a1, b1);
    load_frags(st, c, 3, a1, b1);
    mma_block(acc, a0, b0);
    mma_block(acc, a1, b1);
}

// ---------------------------------------------------------------------------
// Stage A: U[b][j][d] = sum_{w,c} k[b][j+w-1][c] * Wop[d][w*CH+c]
// K = 1536 as 48 BK=32 chunks = 24 superchunks.
// ---------------------------------------------------------------------------
__device__ __forceinline__ void loadA_chunk(uint32_t sbase, int b, int jt, int dt,
                                            int ch, int tid) {
    const int w  = ch >> 4;
    const int c0 = (ch & 15) * 32;
    #pragma unroll
    for (int u = 0; u < 4; ++u) {
        int f = tid + u * 128;             // 0..511
        int row = f >> 2, c16 = f & 3;
        uint32_t so = sw_off(row, c16 * 16);
        int jg = jt + row + w - 1;
        int ok = (jg >= 0 && jg < LK) ? 16 : 0;
        int jc = (jg >= 0 && jg < LK) ? jg : 0;
        size_t gi = ((size_t)b * LK + jc) * CH + c0 + c16 * 8;
        cpa16(sbase + so, g_kh + gi, ok);
        size_t wi = (size_t)(dt + row) * KTOT + w * CH + c0 + c16 * 8;
        cpa16(sbase + OFF_B + so, g_Wh + wi, 16);
    }
}

__device__ __forceinline__ void loadA_super(uint32_t sbase, int b, int jt, int dt,
                                            int sc, int tid) {
    loadA_chunk(sbase,               b, jt, dt, 2 * sc,     tid);
    loadA_chunk(sbase + CHUNK_BYTES, b, jt, dt, 2 * sc + 1, tid);
}

__global__ __launch_bounds__(128, 2) void gemmA_mma() {
    extern __shared__ __align__(16) uint8_t smem[];
    const int b  = blockIdx.z;
    const int jt = blockIdx.y * 128;
    const int dt = blockIdx.x * 128;
    const int tid = threadIdx.x, lane = tid & 31, wid = tid >> 5;
    const int wm = wid >> 1, wn = wid & 1;
    const int g = lane >> 2, t = lane & 3;
    const uint32_t sb = smem_u32(smem);
    const LdmCtx ctx = make_ctx(lane, wm, wn);

    float acc[4][8][4];
    #pragma unroll
    for (int a = 0; a < 4; ++a)
        #pragma unroll
        for (int bq = 0; bq < 8; ++bq)
            #pragma unroll
            for (int c = 0; c < 4; ++c) acc[a][bq][c] = 0.f;

    loadA_super(sb,               b, jt, dt, 0, tid); CP_COMMIT();
    loadA_super(sb + STAGE_BYTES, b, jt, dt, 1, tid); CP_COMMIT();
    for (int sc = 0; sc < 24; ++sc) {
        CP_WAIT1();
        __syncthreads();
        if (sc + 2 < 24)
            loadA_super(sb + (uint32_t)((sc + 2) % NSTAGE) * STAGE_BYTES, b, jt, dt, sc + 2, tid);
        CP_COMMIT();
        compute_super(sb + (uint32_t)(sc % NSTAGE) * STAGE_BYTES, ctx, acc);
    }

    // epilogue: store U as fp16
    #pragma unroll
    for (int mi = 0; mi < 4; ++mi) {
        #pragma unroll
        for (int ni = 0; ni < 8; ++ni) {
            int j0 = jt + wm * 64 + mi * 16 + g;
            int d0 = dt + wn * 64 + ni * 8 + 2 * t;
            #pragma unroll
            for (int rr = 0; rr < 2; ++rr) {
                uint32_t hp = pack_h16(acc[mi][ni][rr * 2 + 0], acc[mi][ni][rr * 2 + 1]);
                size_t o = ((size_t)b * LK + (j0 + rr * 8)) * DIM + d0;
                *reinterpret_cast<uint32_t*>(g_Uh + o) = hp;
            }
        }
    }
}

// ---------------------------------------------------------------------------
// Stage B: out[b][i][j] = q[b][i][:] . U[b][j][:] + qb[b,i] + bbj[b,j] + bias_b
// K = 512 as 16 chunks = 8 superchunks. bbj assembled inline from t0/t1/t2.
// ---------------------------------------------------------------------------
__device__ __forceinline__ void loadB_chunk(uint32_t sbase, int b, int it, int jt,
                                            int ch, int tid) {
    const int kt = ch * 32;
    #pragma unroll
    for (int u = 0; u < 4; ++u) {
        int f = tid + u * 128;
        int row = f >> 2, c16 = f & 3;
        uint32_t so = sw_off(row, c16 * 16);
        size_t qi = ((size_t)b * LQ + it + row) * DIM + kt + c16 * 8;
        cpa16(sbase + so, g_qh + qi, 16);
        size_t ui = ((size_t)b * LK + jt + row) * DIM + kt + c16 * 8;
        cpa16(sbase + OFF_B + so, g_Uh + ui, 16);
    }
}

__device__ __forceinline__ void loadB_super(uint32_t sbase, int b, int it, int jt,
                                            int sc, int tid) {
    loadB_chunk(sbase,               b, it, jt, 2 * sc,     tid);
    loadB_chunk(sbase + CHUNK_BYTES, b, it, jt, 2 * sc + 1, tid);
}

__global__ __launch_bounds__(128, 2) void gemmB_mma(const float* __restrict__ biasb,
                                                    float* __restrict__ out) {
    extern __shared__ __align__(16) uint8_t smem[];
    const int b  = blockIdx.z;
    const int it = blockIdx.y * 128;
    const int jt = blockIdx.x * 128;
    const int tid = threadIdx.x, lane = tid & 31, wid = tid >> 5;
    const int wm = wid >> 1, wn = wid & 1;
    const int g = lane >> 2, t = lane & 3;
    const uint32_t sb = smem_u32(smem);
    const LdmCtx ctx = make_ctx(lane, wm, wn);

    float acc[4][8][4];
    #pragma unroll
    for (int a = 0; a < 4; ++a)
        #pragma unroll
        for (int bq = 0; bq < 8; ++bq)
            #pragma unroll
            for (int c = 0; c < 4; ++c) acc[a][bq][c] = 0.f;

    loadB_super(sb,               b, it, jt, 0, tid); CP_COMMIT();
    loadB_super(sb + STAGE_BYTES, b, it, jt, 1, tid); CP_COMMIT();
    for (int sc = 0; sc < 8; ++sc) {
        CP_WAIT1();
        __syncthreads();
        if (sc + 2 < 8)
            loadB_super(sb + (uint32_t)((sc + 2) % NSTAGE) * STAGE_BYTES, b, it, jt, sc + 2, tid);
        CP_COMMIT();
        compute_super(sb + (uint32_t)(sc % NSTAGE) * STAGE_BYTES, ctx, acc);
    }

    // bbj inline: bbj[b,j] = t0[b,j-1] + t1[b,j] + t2[b,j+1] (edges clipped)
    float bbv[8][2];
    #pragma unroll
    for (int ni = 0; ni < 8; ++ni) {
        #pragma unroll
        for (int jj = 0; jj < 2; ++jj) {
            int j = jt + wn * 64 + ni * 8 + 2 * t + jj;   // 0..1023
            int idx = b * LK + j;
            float s = g_t1[idx];
            if (j > 0)      s += g_t0[idx - 1];
            if (j < LK - 1) s += g_t2[idx + 1];
            bbv[ni][jj] = s;
        }
    }

    const float bB = biasb[0];
    #pragma unroll
    for (int mi = 0; mi < 4; ++mi) {
        int i0 = it + wm * 64 + mi * 16 + g;
        float cb0 = g_qb[b * LQ + i0] + bB;
        float cb1 = g_qb[b * LQ + i0 + 8] + bB;
        #pragma unroll
        for (int ni = 0; ni < 8; ++ni) {
            int j0 = jt + wn * 64 + ni * 8 + 2 * t;
            float2 r0 = make_float2(acc[mi][ni][0] + cb0 + bbv[ni][0],
                                    acc[mi][ni][1] + cb0 + bbv[ni][1]);
            float2 r1 = make_float2(acc[mi][ni][2] + cb1 + bbv[ni][0],
                                    acc[mi][ni][3] + cb1 + bbv[ni][1]);
            *reinterpret_cast<float2*>(out + ((size_t)b * LQ + i0) * LK + j0)     = r0;
            *reinterpret_cast<float2*>(out + ((size_t)b * LQ + i0 + 8) * LK + j0) = r1;
        }
    }
}

// ---------------------------------------------------------------------------
extern "C" void kernel_launch(void* const* d_in, const int* in_sizes, int n_in,
                              void* d_out, int out_size) {
    const float* q     = (const float*)d_in[0];   // (8,1024,512)
    const float* k     = (const float*)d_in[1];   // (8,1024,512)
    const float* W     = (const float*)d_in[2];   // (512,1536)
    const float* bk    = (const float*)d_in[3];   // (1536,)
    const float* Wb    = (const float*)d_in[4];   // (512,1)
    const float* bb    = (const float*)d_in[5];   // (1,)
    const float* biasb = (const float*)d_in[6];   // (1,)
    float* out = (float*)d_out;                   // (8,1024,1024)

    // idempotent, deterministic — no static guard
    cudaFuncSetAttribute(gemmA_mma, cudaFuncAttributeMaxDynamicSharedMemorySize, SMEM_TOTAL);
    cudaFuncSetAttribute(gemmB_mma, cudaFuncAttributeMaxDynamicSharedMemorySize, SMEM_TOTAL);

    // fused single-launch preamble: q/k each read exactly once
    preamble_kernel<<<3072, 256>>>(q, k, W, bk, Wb, bb);

    dim3 gA(DIM / 128, LK / 128, BATCH);          // (4, 8, 8)
    gemmA_mma<<<gA, 128, SMEM_TOTAL>>>();

    dim3 gB(LK / 128, LQ / 128, BATCH);           // (8, 8, 8)
    gemmB_mma<<<gB, 128, SMEM_TOTAL>>>(biasb, out);
}

// round 13
// speedup vs baseline: 6.2653x; 1.0142x over previous
#include <cuda_runtime.h>
#include <cuda_fp16.h>
#include <cstdint>

// Problem shapes (fixed by the dataset)
#define BATCH 8
#define LQ    1024
#define LK    1024
#define DIM   512
#define CH    512
#define KTOT  1536   // 3*CH

// ---------------------------------------------------------------------------
// Scratch (device globals). Referenced ONLY from device code (host-side
// &g_xxx yields the shadow symbol: the round-3/4 bug).
// ---------------------------------------------------------------------------
__device__ __half g_qh[BATCH * LQ * DIM];
__device__ __half g_kh[BATCH * LK * CH];
__device__ __half g_Wh[DIM * KTOT];              // Wop[d][w*CH+c] = W[d, c*3+w]
__device__ __half g_Uh[BATCH * LK * DIM];
__device__ float g_qb[BATCH * LQ];
__device__ float g_t0[BATCH * LK];               // per-row dots for bbj conv
__device__ float g_t1[BATCH * LK];
__device__ float g_t2[BATCH * LK];

// ---------------------------------------------------------------------------
// PTX helpers
// ---------------------------------------------------------------------------
__device__ __forceinline__ void mma16816(float* c,
                                         uint32_t a0, uint32_t a1, uint32_t a2, uint32_t a3,
                                         uint32_t b0, uint32_t b1) {
    asm volatile(
        "mma.sync.aligned.m16n8k16.row.col.f32.f16.f16.f32 "
        "{%0,%1,%2,%3}, {%4,%5,%6,%7}, {%8,%9}, {%0,%1,%2,%3};"
        : "+f"(c[0]), "+f"(c[1]), "+f"(c[2]), "+f"(c[3])
        : "r"(a0), "r"(a1), "r"(a2), "r"(a3), "r"(b0), "r"(b1));
}

__device__ __forceinline__ void ldm4(uint32_t& r0, uint32_t& r1, uint32_t& r2, uint32_t& r3,
                                     uint32_t a) {
    asm volatile("ldmatrix.sync.aligned.m8n8.x4.shared.b16 {%0,%1,%2,%3}, [%4];"
                 : "=r"(r0), "=r"(r1), "=r"(r2), "=r"(r3) : "r"(a));
}

__device__ __forceinline__ uint32_t smem_u32(const void* p) {
    uint32_t a;
    asm("{ .reg .u64 t; cvta.to.shared.u64 t, %1; cvt.u32.u64 %0, t; }" : "=r"(a) : "l"(p));
    return a;
}

__device__ __forceinline__ void cpa16(uint32_t dst, const void* src, int srcsz) {
    asm volatile("cp.async.cg.shared.global [%0], [%1], 16, %2;"
                 :: "r"(dst), "l"(src), "r"(srcsz) : "memory");
}
#define CP_COMMIT() asm volatile("cp.async.commit_group;" ::: "memory")
#define CP_WAIT1()  asm volatile("cp.async.wait_group 1;" ::: "memory")

// smem tile: 128 rows x 64 bytes (32 fp16), XOR-swizzled:
//   phys = row*64 + (kb ^ (((row>>1)&3)<<4))
__device__ __forceinline__ uint32_t sw_off(int row, int kb) {
    return (uint32_t)(row * 64 + (kb ^ (((row >> 1) & 3) << 4)));
}

__device__ __forceinline__ uint32_t pack_h16(float a, float b) {
    return (uint32_t)__half_as_ushort(__float2half_rn(a)) |
           ((uint32_t)__half_as_ushort(__float2half_rn(b)) << 16);
}

// ---------------------------------------------------------------------------
// Fused preamble: single launch, block-range dispatch, 2 rows per warp
// (MLP 8) in the q/k paths.
//   blocks [0,512):     q -> fp16 + qb row dots
//   blocks [512,1024):  k -> fp16 + t0/t1/t2 row dots
//   blocks [1024,2048): W repack -> fp16 (thread per (d,c) triple)
// ---------------------------------------------------------------------------
__global__ void preamble_kernel(const float* __restrict__ q,
                                const float* __restrict__ k,
                                const float* __restrict__ W,
                                const float* __restrict__ bk,
                                const float* __restrict__ Wb,
                                const float* __restrict__ bb) {
    int bid = blockIdx.x;
    int tid = threadIdx.x;
    if (bid < 512) {
        int wpair = (bid * 256 + tid) >> 5;         // 0..4095 -> rows 2w, 2w+1
        int lane  = tid & 31;
        int r0 = 2 * wpair, r1 = r0 + 1;
        const float4* q0  = reinterpret_cast<const float4*>(q) + (size_t)r0 * 128;
        const float4* q1  = reinterpret_cast<const float4*>(q) + (size_t)r1 * 128;
        const float4* wb4 = reinterpret_cast<const float4*>(Wb);
        float s0 = 0.f, s1 = 0.f;
        #pragma unroll
        for (int v = 0; v < 4; ++v) {
            int idx = lane + 32 * v;
            float4 x0 = q0[idx];
            float4 x1 = q1[idx];
            float4 wv = wb4[idx];
            s0 += x0.x * wv.x + x0.y * wv.y + x0.z * wv.z + x0.w * wv.w;
            s1 += x1.x * wv.x + x1.y * wv.y + x1.z * wv.z + x1.w * wv.w;
            reinterpret_cast<uint2*>(g_qh)[(size_t)r0 * 128 + idx] =
                make_uint2(pack_h16(x0.x, x0.y), pack_h16(x0.z, x0.w));
            reinterpret_cast<uint2*>(g_qh)[(size_t)r1 * 128 + idx] =
                make_uint2(pack_h16(x1.x, x1.y), pack_h16(x1.z, x1.w));
        }
        #pragma unroll
        for (int o = 16; o; o >>= 1) {
            s0 += __shfl_down_sync(0xFFFFFFFFu, s0, o);
            s1 += __shfl_down_sync(0xFFFFFFFFu, s1, o);
        }
        if (lane == 0) {
            float b0v = bb[0];
            g_qb[r0] = s0 + b0v;
            g_qb[r1] = s1 + b0v;
        }
    } else if (bid < 1024) {
        int wpair = ((bid - 512) * 256 + tid) >> 5;
        int lane  = tid & 31;
        int r0 = 2 * wpair, r1 = r0 + 1;
        const float4* k0  = reinterpret_cast<const float4*>(k) + (size_t)r0 * 128;
        const float4* k1  = reinterpret_cast<const float4*>(k) + (size_t)r1 * 128;
        const float4* bk4 = reinterpret_cast<const float4*>(bk);
        float a0 = 0.f, a1 = 0.f, a2 = 0.f;      // row r0 dots
        float c0 = 0.f, c1 = 0.f, c2 = 0.f;      // row r1 dots
        #pragma unroll
        for (int v = 0; v < 4; ++v) {
            int idx = lane + 32 * v;              // float4 slot; c0 = 4*idx
            float4 x0 = k0[idx];
            float4 x1 = k1[idx];
            float4 f0 = bk4[3 * idx + 0];
            float4 f1 = bk4[3 * idx + 1];
            float4 f2 = bk4[3 * idx + 2];
            a0 += x0.x * f0.x + x0.y * f0.w + x0.z * f1.z + x0.w * f2.y;
            a1 += x0.x * f0.y + x0.y * f1.x + x0.z * f1.w + x0.w * f2.z;
            a2 += x0.x * f0.z + x0.y * f1.y + x0.z * f2.x + x0.w * f2.w;
            c0 += x1.x * f0.x + x1.y * f0.w + x1.z * f1.z + x1.w * f2.y;
            c1 += x1.x * f0.y + x1.y * f1.x + x1.z * f1.w + x1.w * f2.z;
            c2 += x1.x * f0.z + x1.y * f1.y + x1.z * f2.x + x1.w * f2.w;
            reinterpret_cast<uint2*>(g_kh)[(size_t)r0 * 128 + idx] =
                make_uint2(pack_h16(x0.x, x0.y), pack_h16(x0.z, x0.w));
            reinterpret_cast<uint2*>(g_kh)[(size_t)r1 * 128 + idx] =
                make_uint2(pack_h16(x1.x, x1.y), pack_h16(x1.z, x1.w));
        }
        #pragma unroll
        for (int o = 16; o; o >>= 1) {
            a0 += __shfl_down_sync(0xFFFFFFFFu, a0, o);
            a1 += __shfl_down_sync(0xFFFFFFFFu, a1, o);
            a2 += __shfl_down_sync(0xFFFFFFFFu, a2, o);
            c0 += __shfl_down_sync(0xFFFFFFFFu, c0, o);
            c1 += __shfl_down_sync(0xFFFFFFFFu, c1, o);
            c2 += __shfl_down_sync(0xFFFFFFFFu, c2, o);
        }
        if (lane == 0) {
            g_t0[r0] = a0; g_t1[r0] = a1; g_t2[r0] = a2;
            g_t0[r1] = c0; g_t1[r1] = c1; g_t2[r1] = c2;
        }
    } else {
        // W repack, coalesced: thread handles one (d,c) triple.
        int t3 = (bid - 1024) * 256 + tid;        // 0..262143
        int d  = t3 / CH;
        int cc = t3 % CH;
        const float* src = W + (size_t)d * KTOT + cc * 3;
        float w0 = src[0], w1 = src[1], w2 = src[2];
        size_t dst = (size_t)d * KTOT + cc;
        g_Wh[dst]          = __float2half_rn(w0);
        g_Wh[dst + CH]     = __float2half_rn(w1);
        g_Wh[dst + 2 * CH] = __float2half_rn(w2);
    }
}

// ---------------------------------------------------------------------------
// GEMM core: CTA 128x128, 4 warps (2x2), warp tile 64x64, 128 threads.
// Pure fp16 single product, fp32 accumulators. mma.sync is at its HW issue
// ceiling (~287 TF/s) — mainloop is final.
// ---------------------------------------------------------------------------
#define OFF_B       8192
#define CHUNK_BYTES 16384
#define STAGE_BYTES 32768
#define NSTAGE 3
#define SMEM_TOTAL  (NSTAGE * STAGE_BYTES)

struct LdmCtx {
    int tA[4], xA[4];   // per-mi  (16 m-rows each)
    int tB[4], xB[4];   // per-nii (16 n-rows each)
    int kkA, kkB;       // per-lane k-half byte offsets
};

__device__ __forceinline__ LdmCtx make_ctx(int lane, int wm, int wn) {
    LdmCtx c;
    #pragma unroll
    for (int mi = 0; mi < 4; ++mi) {
        int r = wm * 64 + mi * 16 + ((lane >> 3) & 1) * 8 + (lane & 7);
        c.tA[mi] = r * 64;
        c.xA[mi] = ((r >> 1) & 3) << 4;
    }
    #pragma unroll
    for (int nii = 0; nii < 4; ++nii) {
        int r = wn * 64 + nii * 16 + ((lane >> 4) & 1) * 8 + (lane & 7);
        c.tB[nii] = r * 64;
        c.xB[nii] = ((r >> 1) & 3) << 4;
    }
    c.kkA = (lane >> 4) * 16;          // A: matrices 2,3 take k+8 half
    c.kkB = ((lane >> 3) & 1) * 16;    // B: matrices 1,3 take k+8 half
    return c;
}

__device__ __forceinline__ void load_frags(uint32_t st, const LdmCtx& c, int ks,
                                           uint32_t ah[4][4], uint32_t bh[4][4]) {
    const uint32_t base = st + (uint32_t)(ks >> 1) * CHUNK_BYTES;
    const int kbA = (ks & 1) * 32 + c.kkA;
    const int kbB = (ks & 1) * 32 + c.kkB;
    #pragma unroll
    for (int mi = 0; mi < 4; ++mi)
        ldm4(ah[mi][0], ah[mi][1], ah[mi][2], ah[mi][3],
             base + c.tA[mi] + (uint32_t)(kbA ^ c.xA[mi]));
    #pragma unroll
    for (int nii = 0; nii < 4; ++nii)
        ldm4(bh[nii][0], bh[nii][1], bh[nii][2], bh[nii][3],
             base + OFF_B + c.tB[nii] + (uint32_t)(kbB ^ c.xB[nii]));
}

__device__ __forceinline__ void mma_block(float acc[4][8][4],
                                          uint32_t ah[4][4], uint32_t bh[4][4]) {
    #pragma unroll
    for (int mi = 0; mi < 4; ++mi)
        #pragma unroll
        for (int ni = 0; ni < 8; ++ni)
            mma16816(acc[mi][ni], ah[mi][0], ah[mi][1], ah[mi][2], ah[mi][3],
                     bh[ni >> 1][(ni & 1) * 2], bh[ni >> 1][(ni & 1) * 2 + 1]);
}

__device__ __forceinline__ void compute_super(uint32_t st, const LdmCtx& c,
                                              float acc[4][8][4]) {
    uint32_t a0[4][4], b0[4][4], a1[4][4], b1[4][4];
    load_frags(st, c, 0, a0, b0);
    load_frags(st, c, 1, a1, b1);
    mma_block(acc, a0, b0);
    load_frags(st, c, 2, a0, b0);
    mma_block(acc, a1, b1);
    load_frags(st, c, 3, a1, b1);
    mma_block(acc, a0, b0);
    mma_block(acc, a1, b1);
}

// ---------------------------------------------------------------------------
// Stage A: U[b][j][d] = sum_{w,c} k[b][j+w-1][c] * Wop[d][w*CH+c]
// ---------------------------------------------------------------------------
__device__ __forceinline__ void loadA_chunk(uint32_t sbase, int b, int jt, int dt,
                                            int ch, int tid) {
    const int w  = ch >> 4;
    const int c0 = (ch & 15) * 32;
    #pragma unroll
    for (int u = 0; u < 4; ++u) {
        int f = tid + u * 128;             // 0..511
        int row = f >> 2, c16 = f & 3;
        uint32_t so = sw_off(row, c16 * 16);
        int jg = jt + row + w - 1;
        int ok = (jg >= 0 && jg < LK) ? 16 : 0;
        int jc = (jg >= 0 && jg < LK) ? jg : 0;
        size_t gi = ((size_t)b * LK + jc) * CH + c0 + c16 * 8;
        cpa16(sbase + so, g_kh + gi, ok);
        size_t wi = (size_t)(dt + row) * KTOT + w * CH + c0 + c16 * 8;
        cpa16(sbase + OFF_B + so, g_Wh + wi, 16);
    }
}

__device__ __forceinline__ void loadA_super(uint32_t sbase, int b, int jt, int dt,
                                            int sc, int tid) {
    loadA_chunk(sbase,               b, jt, dt, 2 * sc,     tid);
    loadA_chunk(sbase + CHUNK_BYTES, b, jt, dt, 2 * sc + 1, tid);
}

__global__ __launch_bounds__(128, 2) void gemmA_mma() {
    extern __shared__ __align__(16) uint8_t smem[];
    const int b  = blockIdx.z;
    const int jt = blockIdx.y * 128;
    const int dt = blockIdx.x * 128;
    const int tid = threadIdx.x, lane = tid & 31, wid = tid >> 5;
    const int wm = wid >> 1, wn = wid & 1;
    const int g = lane >> 2, t = lane & 3;
    const uint32_t sb = smem_u32(smem);
    const LdmCtx ctx = make_ctx(lane, wm, wn);

    float acc[4][8][4];
    #pragma unroll
    for (int a = 0; a < 4; ++a)
        #pragma unroll
        for (int bq = 0; bq < 8; ++bq)
            #pragma unroll
            for (int c = 0; c < 4; ++c) acc[a][bq][c] = 0.f;

    loadA_super(sb,               b, jt, dt, 0, tid); CP_COMMIT();
    loadA_super(sb + STAGE_BYTES, b, jt, dt, 1, tid); CP_COMMIT();
    for (int sc = 0; sc < 24; ++sc) {
        CP_WAIT1();
        __syncthreads();
        if (sc + 2 < 24)
            loadA_super(sb + (uint32_t)((sc + 2) % NSTAGE) * STAGE_BYTES, b, jt, dt, sc + 2, tid);
        CP_COMMIT();
        compute_super(sb + (uint32_t)(sc % NSTAGE) * STAGE_BYTES, ctx, acc);
    }

    // epilogue: store U as fp16
    #pragma unroll
    for (int mi = 0; mi < 4; ++mi) {
        #pragma unroll
        for (int ni = 0; ni < 8; ++ni) {
            int j0 = jt + wm * 64 + mi * 16 + g;
            int d0 = dt + wn * 64 + ni * 8 + 2 * t;
            #pragma unroll
            for (int rr = 0; rr < 2; ++rr) {
                uint32_t hp = pack_h16(acc[mi][ni][rr * 2 + 0], acc[mi][ni][rr * 2 + 1]);
                size_t o = ((size_t)b * LK + (j0 + rr * 8)) * DIM + d0;
                *reinterpret_cast<uint32_t*>(g_Uh + o) = hp;
            }
        }
    }
}

// ---------------------------------------------------------------------------
// Stage B: out[b][i][j] = q[b][i][:] . U[b][j][:] + qb[b,i] + bbj[b,j] + bias_b
// ---------------------------------------------------------------------------
__device__ __forceinline__ void loadB_chunk(uint32_t sbase, int b, int it, int jt,
                                            int ch, int tid) {
    const int kt = ch * 32;
    #pragma unroll
    for (int u = 0; u < 4; ++u) {
        int f = tid + u * 128;
        int row = f >> 2, c16 = f & 3;
        uint32_t so = sw_off(row, c16 * 16);
        size_t qi = ((size_t)b * LQ + it + row) * DIM + kt + c16 * 8;
        cpa16(sbase + so, g_qh + qi, 16);
        size_t ui = ((size_t)b * LK + jt + row) * DIM + kt + c16 * 8;
        cpa16(sbase + OFF_B + so, g_Uh + ui, 16);
    }
}

__device__ __forceinline__ void loadB_super(uint32_t sbase, int b, int it, int jt,
                                            int sc, int tid) {
    loadB_chunk(sbase,               b, it, jt, 2 * sc,     tid);
    loadB_chunk(sbase + CHUNK_BYTES, b, it, jt, 2 * sc + 1, tid);
}

__global__ __launch_bounds__(128, 2) void gemmB_mma(const float* __restrict__ biasb,
                                                    float* __restrict__ out) {
    extern __shared__ __align__(16) uint8_t smem[];
    const int b  = blockIdx.z;
    const int it = blockIdx.y * 128;
    const int jt = blockIdx.x * 128;
    const int tid = threadIdx.x, lane = tid & 31, wid = tid >> 5;
    const int wm = wid >> 1, wn = wid & 1;
    const int g = lane >> 2, t = lane & 3;
    const uint32_t sb = smem_u32(smem);
    const LdmCtx ctx = make_ctx(lane, wm, wn);

    float acc[4][8][4];
    #pragma unroll
    for (int a = 0; a < 4; ++a)
        #pragma unroll
        for (int bq = 0; bq < 8; ++bq)
            #pragma unroll
            for (int c = 0; c < 4; ++c) acc[a][bq][c] = 0.f;

    loadB_super(sb,               b, it, jt, 0, tid); CP_COMMIT();
    loadB_super(sb + STAGE_BYTES, b, it, jt, 1, tid); CP_COMMIT();
    for (int sc = 0; sc < 8; ++sc) {
        CP_WAIT1();
        __syncthreads();
        if (sc + 2 < 8)
            loadB_super(sb + (uint32_t)((sc + 2) % NSTAGE) * STAGE_BYTES, b, it, jt, sc + 2, tid);
        CP_COMMIT();
        compute_super(sb + (uint32_t)(sc % NSTAGE) * STAGE_BYTES, ctx, acc);
    }

    // bbj inline: bbj[b,j] = t0[b,j-1] + t1[b,j] + t2[b,j+1] (edges clipped)
    float bbv[8][2];
    #pragma unroll
    for (int ni = 0; ni < 8; ++ni) {
        #pragma unroll
        for (int jj = 0; jj < 2; ++jj) {
            int j = jt + wn * 64 + ni * 8 + 2 * t + jj;   // 0..1023
            int idx = b * LK + j;
            float s = g_t1[idx];
            if (j > 0)      s += g_t0[idx - 1];
            if (j < LK - 1) s += g_t2[idx + 1];
            bbv[ni][jj] = s;
        }
    }

    const float bB = biasb[0];
    #pragma unroll
    for (int mi = 0; mi < 4; ++mi) {
        int i0 = it + wm * 64 + mi * 16 + g;
        float cb0 = g_qb[b * LQ + i0] + bB;
        float cb1 = g_qb[b * LQ + i0 + 8] + bB;
        #pragma unroll
        for (int ni = 0; ni < 8; ++ni) {
            int j0 = jt + wn * 64 + ni * 8 + 2 * t;
            float2 r0 = make_float2(acc[mi][ni][0] + cb0 + bbv[ni][0],
                                    acc[mi][ni][1] + cb0 + bbv[ni][1]);
            float2 r1 = make_float2(acc[mi][ni][2] + cb1 + bbv[ni][0],
                                    acc[mi][ni][3] + cb1 + bbv[ni][1]);
            *reinterpret_cast<float2*>(out + ((size_t)b * LQ + i0) * LK + j0)     = r0;
            *reinterpret_cast<float2*>(out + ((size_t)b * LQ + i0 + 8) * LK + j0) = r1;
        }
    }
}

// ---------------------------------------------------------------------------
extern "C" void kernel_launch(void* const* d_in, const int* in_sizes, int n_in,
                              void* d_out, int out_size) {
    const float* q     = (const float*)d_in[0];   // (8,1024,512)
    const float* k     = (const float*)d_in[1];   // (8,1024,512)
    const float* W     = (const float*)d_in[2];   // (512,1536)
    const float* bk    = (const float*)d_in[3];   // (1536,)
    const float* Wb    = (const float*)d_in[4];   // (512,1)
    const float* bb    = (const float*)d_in[5];   // (1,)
    const float* biasb = (const float*)d_in[6];   // (1,)
    float* out = (float*)d_out;                   // (8,1024,1024)

    // idempotent, deterministic — no static guard
    cudaFuncSetAttribute(gemmA_mma, cudaFuncAttributeMaxDynamicSharedMemorySize, SMEM_TOTAL);
    cudaFuncSetAttribute(gemmB_mma, cudaFuncAttributeMaxDynamicSharedMemorySize, SMEM_TOTAL);

    // fused single-launch preamble, 2 rows/warp (MLP 8)
    preamble_kernel<<<2048, 256>>>(q, k, W, bk, Wb, bb);

    dim3 gA(DIM / 128, LK / 128, BATCH);          // (4, 8, 8)
    gemmA_mma<<<gA, 128, SMEM_TOTAL>>>();

    dim3 gB(LK / 128, LQ / 128, BATCH);           // (8, 8, 8)
    gemmB_mma<<<gB, 128, SMEM_TOTAL>>>(biasb, out);
}